// round 7
// baseline (speedup 1.0000x reference)
#include <cuda_runtime.h>
#include <cuda_fp16.h>
#include <math.h>
#include <stdint.h>

// ---------------------------------------------------------------------------
// Problem constants
// ---------------------------------------------------------------------------
#define BB   2
#define TT   2048
#define DD   1024
#define HH   16
#define HDIM 4096
#define VV   32000
#define LL   4
#define MM   (BB*TT)      // 4096 rows
#define QKVD (3*DD)       // 3072

// ---------------------------------------------------------------------------
// Static device scratch (no allocations allowed)
// ---------------------------------------------------------------------------
__device__ float g_x  [MM*DD];
__device__ float g_qkv[MM*QKVD];
__device__ __half g_xnh[MM*DD],  g_xnl[MM*DD];
__device__ __half g_yh [MM*DD],  g_yl [MM*DD];
__device__ __half g_hh [MM*HDIM], g_hl [MM*HDIM];
__device__ __half g_xh [MM*DD],  g_xl [MM*DD];
// single-term fp16 weights (recomputed every launch — weights are inputs)
__device__ __half g_wqkv[LL*QKVD*DD];
__device__ __half g_wo  [LL*DD*DD];
__device__ __half g_w1  [LL*HDIM*DD];
__device__ __half g_w2  [LL*DD*HDIM];
__device__ __half g_ro  [VV*DD];

// ---------------------------------------------------------------------------
// helpers (base-target PTX only: cp.async, ldmatrix, mma.sync)
// ---------------------------------------------------------------------------
__device__ __forceinline__ uint32_t smem_u32(const void* p) {
    uint32_t a;
    asm("{ .reg .u64 t; cvta.to.shared.u64 t, %1; cvt.u32.u64 %0, t; }"
        : "=r"(a) : "l"(p));
    return a;
}
__device__ __forceinline__ void cp16(uint32_t dst, const void* src) {
    asm volatile("cp.async.cg.shared.global [%0], [%1], 16;" :: "r"(dst), "l"(src));
}
#define CP_COMMIT()  asm volatile("cp.async.commit_group;" ::: "memory")
#define CP_WAIT0()   asm volatile("cp.async.wait_group 0;" ::: "memory")
#define CP_WAIT1()   asm volatile("cp.async.wait_group 1;" ::: "memory")

__device__ __forceinline__ void ldsm4(uint32_t& r0, uint32_t& r1,
                                      uint32_t& r2, uint32_t& r3, uint32_t addr) {
    asm volatile("ldmatrix.sync.aligned.m8n8.x4.shared.b16 {%0,%1,%2,%3}, [%4];"
                 : "=r"(r0), "=r"(r1), "=r"(r2), "=r"(r3) : "r"(addr));
}
__device__ __forceinline__ void mma16816(float* d, const uint32_t* a, const uint32_t* b) {
    asm volatile("mma.sync.aligned.m16n8k16.row.col.f32.f16.f16.f32 "
        "{%0,%1,%2,%3}, {%4,%5,%6,%7}, {%8,%9}, {%0,%1,%2,%3};"
        : "+f"(d[0]), "+f"(d[1]), "+f"(d[2]), "+f"(d[3])
        : "r"(a[0]), "r"(a[1]), "r"(a[2]), "r"(a[3]), "r"(b[0]), "r"(b[1]));
}
__device__ __forceinline__ void split2(float v, __half& h, __half& l) {
    h = __float2half(v);
    l = __float2half(v - __half2float(h));
}

// ---------------------------------------------------------------------------
// HMMA GEMM: C[M,N] (+)= (Ah+Al)[M,K] * B^T (+bias)(relu), B stored [N,K] fp16.
// A is 2-term fp16 (hi/lo), B single fp16 -> 2 MMAs per k16.
// CTA 128(M)x128(N), 128 threads = 4 warps as 2(m)x2(n) -> 64x64 warp tiles.
// K-chunk 32, 3-stage cp.async pipeline, 90KB smem -> 2 CTAs/SM (ping-pong
// across barriers hides cp.async-wait + LDSM latency).
// grid.x = M-block (fast), grid.y = N-block (slow) -> weight L2 reuse.
// ---------------------------------------------------------------------------
#define STAGES  3
#define KC      32
#define PITCH   80u                    // 64B data + 16B pad per 32-fp16 row
#define A_TILE  (128u * PITCH)         // 10240
#define B_TILE  (128u * PITCH)         // 10240
#define STAGE_B (3u * A_TILE)          // 30720: Ah | Al | Bh
#define SMEM_B  (STAGES * STAGE_B)     // 92160

template<bool BIAS, bool RELU, bool ACCUM, bool SPLIT>
__global__ __launch_bounds__(128, 2)
void gemm_mma(const __half* __restrict__ Ah, const __half* __restrict__ Al,
              const __half* __restrict__ Bh,
              const float* __restrict__ bias,
              float* __restrict__ C,
              __half* __restrict__ Ch, __half* __restrict__ Cl,
              int M, int N, int K)
{
    extern __shared__ char smem_raw[];
    const uint32_t sb = smem_u32(smem_raw);

    const int tid  = threadIdx.x;
    const int wid  = tid >> 5;
    const int lane = tid & 31;
    const int row0 = blockIdx.x * 128;     // M fast
    const int col0 = blockIdx.y * 128;     // N slow
    const int NC   = K / KC;

    // stage loader: A 1024 cp16 (8/thread), B 512 cp16 (4/thread)
    auto load_stage = [&](int s) {
        const uint32_t stg = sb + (uint32_t)(s % STAGES) * STAGE_B;
        const int k0 = s * KC;
        #pragma unroll
        for (int i = 0; i < 8; i++) {
            int f = i * 128 + tid;              // 0..1023
            int sub = f >> 9;                   // 0:Ah 1:Al
            int rem = f & 511;
            int r = rem >> 2, c = rem & 3;
            const __half* src = ((sub == 0) ? Ah : Al)
                              + (size_t)(row0 + r) * K + k0 + c * 8;
            cp16(stg + (uint32_t)sub * A_TILE + (uint32_t)r * PITCH + c * 16, src);
        }
        #pragma unroll
        for (int i = 0; i < 4; i++) {
            int f = i * 128 + tid;              // 0..511
            int r = f >> 2, c = f & 3;
            const __half* src = Bh + (size_t)(col0 + r) * K + k0 + c * 8;
            cp16(stg + 2u*A_TILE + (uint32_t)r * PITCH + c * 16, src);
        }
        CP_COMMIT();
    };

    load_stage(0);
    if (NC > 1) load_stage(1);

    const int wm = wid >> 1;   // 0..1 -> 64-row block
    const int wn = wid & 1;    // 0..1 -> 64-col block

    float acc[4][8][4];
    #pragma unroll
    for (int a = 0; a < 4; a++)
        #pragma unroll
        for (int b = 0; b < 8; b++)
            #pragma unroll
            for (int c = 0; c < 4; c++) acc[a][b][c] = 0.f;

    for (int i = 0; i < NC; i++) {
        if (i < NC - 1) CP_WAIT1(); else CP_WAIT0();
        __syncthreads();
        if (i + 2 < NC) load_stage(i + 2);   // buffer (i-1)%3 — compute done

        const uint32_t stg  = sb + (uint32_t)(i % STAGES) * STAGE_B;
        const uint32_t ah_b = stg;
        const uint32_t al_b = stg + A_TILE;
        const uint32_t bh_b = stg + 2u*A_TILE;

        #pragma unroll
        for (int ks = 0; ks < 2; ks++) {
            uint32_t ah[4][4], al[4][4], bf[8][2];
            const uint32_t a_coff = (uint32_t)ks * 32 + ((lane >> 4) << 4);
            #pragma unroll
            for (int mi = 0; mi < 4; mi++) {
                uint32_t r = (uint32_t)(wm * 64 + mi * 16 + (lane & 15));
                ldsm4(ah[mi][0], ah[mi][1], ah[mi][2], ah[mi][3], ah_b + r * PITCH + a_coff);
                ldsm4(al[mi][0], al[mi][1], al[mi][2], al[mi][3], al_b + r * PITCH + a_coff);
            }
            const uint32_t b_coff = (uint32_t)ks * 32 + (((lane >> 3) & 1) << 4);
            #pragma unroll
            for (int g = 0; g < 4; g++) {
                uint32_t r = (uint32_t)(wn * 64 + g * 16 + (lane & 7) + ((lane >> 4) << 3));
                ldsm4(bf[2*g][0], bf[2*g][1], bf[2*g+1][0], bf[2*g+1][1], bh_b + r * PITCH + b_coff);
            }
            #pragma unroll
            for (int mi = 0; mi < 4; mi++)
                #pragma unroll
                for (int ni = 0; ni < 8; ni++) {
                    mma16816(acc[mi][ni], ah[mi], bf[ni]);
                    mma16816(acc[mi][ni], al[mi], bf[ni]);
                }
        }
    }

    // ---- epilogue ----
    #pragma unroll
    for (int mi = 0; mi < 4; mi++) {
        #pragma unroll
        for (int rg = 0; rg < 2; rg++) {
            int r = row0 + wm * 64 + mi * 16 + (lane >> 2) + rg * 8;
            #pragma unroll
            for (int ni = 0; ni < 8; ni++) {
                int c = col0 + wn * 64 + ni * 8 + (lane & 3) * 2;
                float v0 = acc[mi][ni][rg * 2 + 0];
                float v1 = acc[mi][ni][rg * 2 + 1];
                if (BIAS)  { v0 += bias[c]; v1 += bias[c + 1]; }
                if (RELU)  { v0 = fmaxf(v0, 0.f); v1 = fmaxf(v1, 0.f); }
                if (ACCUM) {
                    float2 o = *(const float2*)&C[(size_t)r * N + c];
                    v0 += o.x; v1 += o.y;
                }
                if (SPLIT) {
                    __half h0, l0, h1, l1;
                    split2(v0, h0, l0); split2(v1, h1, l1);
                    *(__half2*)&Ch[(size_t)r * N + c] = __halves2half2(h0, h1);
                    *(__half2*)&Cl[(size_t)r * N + c] = __halves2half2(l0, l1);
                } else {
                    *(float2*)&C[(size_t)r * N + c] = make_float2(v0, v1);
                }
            }
        }
    }
}

// ---------------------------------------------------------------------------
// Fused embedding + positional encoding + LayerNorm(ln1, layer 0).
// ---------------------------------------------------------------------------
__global__ __launch_bounds__(256) void embed_ln_kernel(const int* __restrict__ tokens,
                                                       const float* __restrict__ emb,
                                                       const float* __restrict__ w,
                                                       const float* __restrict__ b,
                                                       float* __restrict__ x,
                                                       __half* __restrict__ yh,
                                                       __half* __restrict__ yl)
{
    __shared__ float red[8];
    int row = blockIdx.x;
    int tid = threadIdx.x;
    int bb  = row >> 11;
    int t   = row & (TT - 1);
    int tok = (t == 0) ? 0 : tokens[bb * TT + t - 1];

    int c = tid * 4;
    float v[4];
    #pragma unroll
    for (int j = 0; j < 4; j++) {
        int d = c + j;
        int k = d & 1;
        double e = (double)(d - k) / (double)DD;
        float freq = (float)exp(-e * 11.512925464970229);   // LEN_MAX^-e
        float arg = (float)t * freq + 1.5707963267948966f * (float)k;
        v[j] = emb[(size_t)tok * DD + d] + sinf(arg);
    }
    *(float4*)&x[(size_t)row * DD + c] = make_float4(v[0], v[1], v[2], v[3]);

    float s = v[0] + v[1] + v[2] + v[3];
    #pragma unroll
    for (int o = 16; o > 0; o >>= 1) s += __shfl_xor_sync(0xffffffffu, s, o);
    if ((tid & 31) == 0) red[tid >> 5] = s;
    __syncthreads();
    float tot = 0.f;
    #pragma unroll
    for (int i = 0; i < 8; i++) tot += red[i];
    float mean = tot * (1.0f / DD);
    __syncthreads();

    float dx0 = v[0]-mean, dx1 = v[1]-mean, dx2 = v[2]-mean, dx3 = v[3]-mean;
    float s2 = dx0*dx0 + dx1*dx1 + dx2*dx2 + dx3*dx3;
    #pragma unroll
    for (int o = 16; o > 0; o >>= 1) s2 += __shfl_xor_sync(0xffffffffu, s2, o);
    if ((tid & 31) == 0) red[tid >> 5] = s2;
    __syncthreads();
    float tot2 = 0.f;
    #pragma unroll
    for (int i = 0; i < 8; i++) tot2 += red[i];
    float inv = rsqrtf(tot2 * (1.0f / DD) + 1e-5f);

    float4 wv = *(const float4*)&w[c];
    float4 bv = *(const float4*)&b[c];
    float o0 = dx0 * inv * wv.x + bv.x;
    float o1 = dx1 * inv * wv.y + bv.y;
    float o2 = dx2 * inv * wv.z + bv.z;
    float o3 = dx3 * inv * wv.w + bv.w;
    __half h0, l0, h1, l1, h2, l2, h3, l3;
    split2(o0, h0, l0); split2(o1, h1, l1); split2(o2, h2, l2); split2(o3, h3, l3);
    size_t off = (size_t)row * DD + c;
    *(__half2*)&yh[off]     = __halves2half2(h0, h1);
    *(__half2*)&yh[off + 2] = __halves2half2(h2, h3);
    *(__half2*)&yl[off]     = __halves2half2(l0, l1);
    *(__half2*)&yl[off + 2] = __halves2half2(l2, l3);
}

// ---------------------------------------------------------------------------
// LayerNorm -> split fp16 hi/lo output
// ---------------------------------------------------------------------------
__global__ __launch_bounds__(256) void ln_split_kernel(const float* __restrict__ x,
                                                       __half* __restrict__ yh,
                                                       __half* __restrict__ yl,
                                                       const float* __restrict__ w,
                                                       const float* __restrict__ b)
{
    __shared__ float red[8];
    int row = blockIdx.x;
    int tid = threadIdx.x;
    const float* xr = x + (size_t)row * DD;
    float4 xv = *(const float4*)&xr[tid * 4];

    float s = xv.x + xv.y + xv.z + xv.w;
    #pragma unroll
    for (int o = 16; o > 0; o >>= 1) s += __shfl_xor_sync(0xffffffffu, s, o);
    if ((tid & 31) == 0) red[tid >> 5] = s;
    __syncthreads();
    float tot = 0.f;
    #pragma unroll
    for (int i = 0; i < 8; i++) tot += red[i];
    float mean = tot * (1.0f / DD);
    __syncthreads();

    float dx0 = xv.x - mean, dx1 = xv.y - mean, dx2 = xv.z - mean, dx3 = xv.w - mean;
    float s2 = dx0*dx0 + dx1*dx1 + dx2*dx2 + dx3*dx3;
    #pragma unroll
    for (int o = 16; o > 0; o >>= 1) s2 += __shfl_xor_sync(0xffffffffu, s2, o);
    if ((tid & 31) == 0) red[tid >> 5] = s2;
    __syncthreads();
    float tot2 = 0.f;
    #pragma unroll
    for (int i = 0; i < 8; i++) tot2 += red[i];
    float inv = rsqrtf(tot2 * (1.0f / DD) + 1e-5f);

    int c = tid * 4;
    float4 wv = *(const float4*)&w[c];
    float4 bv = *(const float4*)&b[c];
    float o0 = dx0 * inv * wv.x + bv.x;
    float o1 = dx1 * inv * wv.y + bv.y;
    float o2 = dx2 * inv * wv.z + bv.z;
    float o3 = dx3 * inv * wv.w + bv.w;
    __half h0, l0, h1, l1, h2, l2, h3, l3;
    split2(o0, h0, l0); split2(o1, h1, l1); split2(o2, h2, l2); split2(o3, h3, l3);
    size_t off = (size_t)row * DD + c;
    *(__half2*)&yh[off]     = __halves2half2(h0, h1);
    *(__half2*)&yh[off + 2] = __halves2half2(h2, h3);
    *(__half2*)&yl[off]     = __halves2half2(l0, l1);
    *(__half2*)&yl[off + 2] = __halves2half2(l2, l3);
}

// ---------------------------------------------------------------------------
// Causal attention over packed qkv [M, 3072], outputs split fp16 y.
// ---------------------------------------------------------------------------
__global__ __launch_bounds__(64) void attn_kernel(const float* __restrict__ QKV,
                                                  __half* __restrict__ Yh,
                                                  __half* __restrict__ Yl)
{
    __shared__ float Ks[64][64];
    __shared__ float S[64][65];

    const int bh = blockIdx.y;
    const int b  = bh / HH;
    const int h  = bh % HH;
    const int qt = blockIdx.x;
    const int tid = threadIdx.x;
    const int t = qt * 64 + tid;
    const float scale = 0.125f;

    float q[64];
    const float* qp = QKV + (size_t)(b * TT + t) * QKVD + h * 64;
    #pragma unroll
    for (int i = 0; i < 64; i += 4) {
        float4 v4 = *(const float4*)&qp[i];
        q[i] = v4.x; q[i+1] = v4.y; q[i+2] = v4.z; q[i+3] = v4.w;
    }

    float m = -1e30f, l = 0.f;
    float acc[64];
    #pragma unroll
    for (int i = 0; i < 64; i++) acc[i] = 0.f;

    for (int s0 = 0; s0 <= qt * 64; s0 += 64) {
        __syncthreads();
        #pragma unroll
        for (int it = 0; it < 16; it++) {
            int f = it * 64 + tid;
            int r = f >> 4, c4 = (f & 15) << 2;
            *(float4*)&Ks[r][c4] =
                *(const float4*)&QKV[(size_t)(b * TT + s0 + r) * QKVD + DD + h * 64 + c4];
        }
        __syncthreads();

        float mx = -1e30f;
        for (int s = 0; s < 64; s++) {
            float d0 = 0.f, d1 = 0.f, d2 = 0.f, d3 = 0.f;
            #pragma unroll
            for (int i = 0; i < 64; i += 16) {
                float4 k0 = *(const float4*)&Ks[s][i];
                float4 k1 = *(const float4*)&Ks[s][i + 4];
                float4 k2 = *(const float4*)&Ks[s][i + 8];
                float4 k3 = *(const float4*)&Ks[s][i + 12];
                d0 += q[i+0]*k0.x + q[i+1]*k0.y + q[i+2]*k0.z + q[i+3]*k0.w;
                d1 += q[i+4]*k1.x + q[i+5]*k1.y + q[i+6]*k1.z + q[i+7]*k1.w;
                d2 += q[i+8]*k2.x + q[i+9]*k2.y + q[i+10]*k2.z + q[i+11]*k2.w;
                d3 += q[i+12]*k3.x + q[i+13]*k3.y + q[i+14]*k3.z + q[i+15]*k3.w;
            }
            float dsc = ((d0 + d1) + (d2 + d3)) * scale;
            if (s0 + s > t) dsc = -1e30f;
            S[tid][s] = dsc;
            mx = fmaxf(mx, dsc);
        }

        float mnew = fmaxf(m, mx);
        float corr = __expf(m - mnew);
        l *= corr;
        #pragma unroll
        for (int i = 0; i < 64; i++) acc[i] *= corr;
        float lsum = 0.f;
        for (int s = 0; s < 64; s++) {
            float p = __expf(S[tid][s] - mnew);
            S[tid][s] = p;
            lsum += p;
        }
        l += lsum;
        m = mnew;

        __syncthreads();
        #pragma unroll
        for (int it = 0; it < 16; it++) {
            int f = it * 64 + tid;
            int r = f >> 4, c4 = (f & 15) << 2;
            *(float4*)&Ks[r][c4] =
                *(const float4*)&QKV[(size_t)(b * TT + s0 + r) * QKVD + 2 * DD + h * 64 + c4];
        }
        __syncthreads();

        for (int s = 0; s < 64; s++) {
            float p = S[tid][s];
            #pragma unroll
            for (int i = 0; i < 64; i += 4) {
                float4 vv = *(const float4*)&Ks[s][i];
                acc[i+0] += p * vv.x;
                acc[i+1] += p * vv.y;
                acc[i+2] += p * vv.z;
                acc[i+3] += p * vv.w;
            }
        }
    }

    float inv = 1.0f / l;
    size_t yoff = (size_t)(b * TT + t) * DD + h * 64;
    #pragma unroll
    for (int i = 0; i < 64; i += 2) {
        __half h0, l0, h1, l1;
        split2(acc[i] * inv, h0, l0);
        split2(acc[i+1] * inv, h1, l1);
        *(__half2*)&Yh[yoff + i] = __halves2half2(h0, h1);
        *(__half2*)&Yl[yoff + i] = __halves2half2(l0, l1);
    }
}

// ---------------------------------------------------------------------------
// Weight conversion kernels (single fp16, vectorized x4)
// ---------------------------------------------------------------------------
__global__ void conv_kernel(const float* __restrict__ s,
                            __half* __restrict__ h, int n4)
{
    int i = blockIdx.x * blockDim.x + threadIdx.x;
    if (i >= n4) return;
    float4 v = *(const float4*)&s[i * 4];
    *(__half2*)&h[i*4]   = __halves2half2(__float2half(v.x), __float2half(v.y));
    *(__half2*)&h[i*4+2] = __halves2half2(__float2half(v.z), __float2half(v.w));
}

__global__ void pack_qkv_kernel(const float* __restrict__ wq,
                                const float* __restrict__ wk,
                                const float* __restrict__ wv,
                                __half* __restrict__ h)
{
    int i = blockIdx.x * blockDim.x + threadIdx.x;   // x4 elements
    const int per_layer4 = QKVD * DD / 4;
    if (i >= LL * per_layer4) return;
    int lyr = i / per_layer4;
    int rem = i - lyr * per_layer4;
    int row = rem >> 8;                      // 0..3071
    int c4  = rem & 255;
    int which = row >> 10;
    int srow  = row & 1023;
    const float* src = (which == 0) ? wq : ((which == 1) ? wk : wv);
    float4 v = *(const float4*)&src[(size_t)lyr * (DD*DD) + (size_t)srow * DD + c4 * 4];
    size_t o = (size_t)i * 4;
    *(__half2*)&h[o]   = __halves2half2(__float2half(v.x), __float2half(v.y));
    *(__half2*)&h[o+2] = __halves2half2(__float2half(v.z), __float2half(v.w));
}

__global__ void transpose_wo_kernel(const float* __restrict__ wo,
                                    __half* __restrict__ h)
{
    int i = blockIdx.x * blockDim.x + threadIdx.x;
    if (i >= LL * DD * DD) return;
    int lyr = i >> 20;
    int rem = i & ((1 << 20) - 1);
    int nrow = rem >> 10;
    int kcol = rem & 1023;
    h[i] = __float2half(wo[((size_t)lyr << 20) + ((size_t)kcol << 10) + nrow]);
}

// ---------------------------------------------------------------------------
// Launch
// ---------------------------------------------------------------------------
extern "C" void kernel_launch(void* const* d_in, const int* in_sizes, int n_in,
                              void* d_out, int out_size)
{
    const int*   tokens = (const int*)  d_in[0];
    const float* emb    = (const float*)d_in[1];
    const float* ln1_w  = (const float*)d_in[2];
    const float* ln1_b  = (const float*)d_in[3];
    const float* w_q    = (const float*)d_in[4];
    const float* w_k    = (const float*)d_in[5];
    const float* w_v    = (const float*)d_in[6];
    const float* w_o    = (const float*)d_in[7];
    const float* ln2_w  = (const float*)d_in[8];
    const float* ln2_b  = (const float*)d_in[9];
    const float* w1     = (const float*)d_in[10];
    const float* b1     = (const float*)d_in[11];
    const float* w2     = (const float*)d_in[12];
    const float* b2     = (const float*)d_in[13];
    const float* ro_w   = (const float*)d_in[14];
    const float* ro_b   = (const float*)d_in[15];
    float* out = (float*)d_out;

    float *x, *qkv;
    __half *xnh, *xnl, *yh, *yl, *hh, *hl, *xh, *xl;
    __half *wqkv, *wo, *w1w, *w2w, *ro;
    cudaGetSymbolAddress((void**)&x,    g_x);
    cudaGetSymbolAddress((void**)&qkv,  g_qkv);
    cudaGetSymbolAddress((void**)&xnh,  g_xnh);  cudaGetSymbolAddress((void**)&xnl, g_xnl);
    cudaGetSymbolAddress((void**)&yh,   g_yh);   cudaGetSymbolAddress((void**)&yl,  g_yl);
    cudaGetSymbolAddress((void**)&hh,   g_hh);   cudaGetSymbolAddress((void**)&hl,  g_hl);
    cudaGetSymbolAddress((void**)&xh,   g_xh);   cudaGetSymbolAddress((void**)&xl,  g_xl);
    cudaGetSymbolAddress((void**)&wqkv, g_wqkv);
    cudaGetSymbolAddress((void**)&wo,   g_wo);
    cudaGetSymbolAddress((void**)&w1w,  g_w1);
    cudaGetSymbolAddress((void**)&w2w,  g_w2);
    cudaGetSymbolAddress((void**)&ro,   g_ro);

    cudaFuncSetAttribute((const void*)gemm_mma<false,false,false,false>,
                         cudaFuncAttributeMaxDynamicSharedMemorySize, SMEM_B);
    cudaFuncSetAttribute((const void*)gemm_mma<false,false,true,false>,
                         cudaFuncAttributeMaxDynamicSharedMemorySize, SMEM_B);
    cudaFuncSetAttribute((const void*)gemm_mma<true,true,false,true>,
                         cudaFuncAttributeMaxDynamicSharedMemorySize, SMEM_B);
    cudaFuncSetAttribute((const void*)gemm_mma<true,false,true,false>,
                         cudaFuncAttributeMaxDynamicSharedMemorySize, SMEM_B);
    cudaFuncSetAttribute((const void*)gemm_mma<true,false,true,true>,
                         cudaFuncAttributeMaxDynamicSharedMemorySize, SMEM_B);
    cudaFuncSetAttribute((const void*)gemm_mma<true,false,false,false>,
                         cudaFuncAttributeMaxDynamicSharedMemorySize, SMEM_B);

    // grid: x = M-block (fast), y = N-block (slow)
    const dim3 gQKV(MM/128, QKVD/128);    // 32 x 24
    const dim3 gD  (MM/128, DD/128);      // 32 x 8
    const dim3 gH  (MM/128, HDIM/128);    // 32 x 32
    const dim3 gV  (MM/128, VV/128);      // 32 x 250
    const dim3 gA  (TT/64, BB*HH);

    // Launch order places the QKV GEMM at graph index 3 (the slot ncu has
    // been capturing across rounds).
    pack_qkv_kernel<<<(LL*QKVD*DD/4 + 255)/256, 256>>>(w_q, w_k, w_v, wqkv);          // 0
    embed_ln_kernel<<<MM, 256>>>(tokens, emb, ln1_w, ln1_b, x, xnh, xnl);             // 1
    transpose_wo_kernel<<<(LL*DD*DD + 255)/256, 256>>>(w_o, wo);                       // 2
    gemm_mma<false,false,false,false><<<gQKV, 128, SMEM_B>>>(                          // 3
        xnh, xnl, wqkv, nullptr, qkv, nullptr, nullptr, MM, QKVD, DD);
    conv_kernel<<<(LL*HDIM*DD/4 + 255)/256, 256>>>(w1, w1w, LL*HDIM*DD/4);            // 4
    conv_kernel<<<(LL*DD*HDIM/4 + 255)/256, 256>>>(w2, w2w, LL*DD*HDIM/4);            // 5
    conv_kernel<<<(VV*DD/4 + 255)/256, 256>>>(ro_w, ro, VV*DD/4);                     // 6

    for (int l = 0; l < LL; l++) {
        const __half* wqkv_l = wqkv + (size_t)l * QKVD * DD;
        const __half* wo_l   = wo   + (size_t)l * DD * DD;
        const __half* w1_l   = w1w  + (size_t)l * HDIM * DD;
        const __half* w2_l   = w2w  + (size_t)l * DD * HDIM;

        if (l > 0) {
            ln_split_kernel<<<MM, 256>>>(x, xnh, xnl, ln1_w + (size_t)l*DD, ln1_b + (size_t)l*DD);
            gemm_mma<false,false,false,false><<<gQKV, 128, SMEM_B>>>(
                xnh, xnl, wqkv_l, nullptr, qkv, nullptr, nullptr, MM, QKVD, DD);
        }

        attn_kernel<<<gA, 64>>>(qkv, yh, yl);

        gemm_mma<false,false,true,false><<<gD, 128, SMEM_B>>>(
            yh, yl, wo_l, nullptr, x, nullptr, nullptr, MM, DD, DD);

        ln_split_kernel<<<MM, 256>>>(x, xnh, xnl, ln2_w + (size_t)l*DD, ln2_b + (size_t)l*DD);

        gemm_mma<true,true,false,true><<<gH, 128, SMEM_B>>>(
            xnh, xnl, w1_l, b1 + (size_t)l*HDIM, nullptr, hh, hl, MM, HDIM, DD);

        if (l < LL - 1) {
            gemm_mma<true,false,true,false><<<gD, 128, SMEM_B>>>(
                hh, hl, w2_l, b2 + (size_t)l*DD, x, nullptr, nullptr, MM, DD, HDIM);
        } else {
            // last layer: fuse readout-input split into the accumulate epilogue
            gemm_mma<true,false,true,true><<<gD, 128, SMEM_B>>>(
                hh, hl, w2_l, b2 + (size_t)l*DD, x, xh, xl, MM, DD, HDIM);
        }
    }

    // readout: out = x @ ro_w^T + ro_b
    gemm_mma<true,false,false,false><<<gV, 128, SMEM_B>>>(
        xh, xl, ro, ro_b, out, nullptr, nullptr, MM, VV, DD);
}

// round 8
// speedup vs baseline: 1.5925x; 1.5925x over previous
#include <cuda_runtime.h>
#include <cuda_fp16.h>
#include <math.h>
#include <stdint.h>

// ---------------------------------------------------------------------------
// Problem constants
// ---------------------------------------------------------------------------
#define BB   2
#define TT   2048
#define DD   1024
#define HH   16
#define HDIM 4096
#define VV   32000
#define LL   4
#define MM   (BB*TT)      // 4096 rows
#define QKVD (3*DD)       // 3072

// ---------------------------------------------------------------------------
// Static device scratch (no allocations allowed)
// ---------------------------------------------------------------------------
__device__ float g_x  [MM*DD];
__device__ __half g_qkvh[MM*QKVD], g_qkvl[MM*QKVD];
__device__ __half g_xnh[MM*DD],  g_xnl[MM*DD];
__device__ __half g_yh [MM*DD],  g_yl [MM*DD];
__device__ __half g_hh [MM*HDIM], g_hl [MM*HDIM];
__device__ __half g_xh [MM*DD],  g_xl [MM*DD];
// single-term fp16 weights (recomputed every launch — weights are inputs)
__device__ __half g_wqkv[LL*QKVD*DD];
__device__ __half g_wo  [LL*DD*DD];
__device__ __half g_w1  [LL*HDIM*DD];
__device__ __half g_w2  [LL*DD*HDIM];
__device__ __half g_ro  [VV*DD];

// ---------------------------------------------------------------------------
// helpers (base-target PTX only: cp.async, ldmatrix, mma.sync)
// ---------------------------------------------------------------------------
__device__ __forceinline__ uint32_t smem_u32(const void* p) {
    uint32_t a;
    asm("{ .reg .u64 t; cvta.to.shared.u64 t, %1; cvt.u32.u64 %0, t; }"
        : "=r"(a) : "l"(p));
    return a;
}
__device__ __forceinline__ void cp16(uint32_t dst, const void* src) {
    asm volatile("cp.async.cg.shared.global [%0], [%1], 16;" :: "r"(dst), "l"(src));
}
#define CP_COMMIT()  asm volatile("cp.async.commit_group;" ::: "memory")
#define CP_WAIT0()   asm volatile("cp.async.wait_group 0;" ::: "memory")
#define CP_WAIT1()   asm volatile("cp.async.wait_group 1;" ::: "memory")

__device__ __forceinline__ void ldsm4(uint32_t& r0, uint32_t& r1,
                                      uint32_t& r2, uint32_t& r3, uint32_t addr) {
    asm volatile("ldmatrix.sync.aligned.m8n8.x4.shared.b16 {%0,%1,%2,%3}, [%4];"
                 : "=r"(r0), "=r"(r1), "=r"(r2), "=r"(r3) : "r"(addr));
}
__device__ __forceinline__ void ldsm4t(uint32_t& r0, uint32_t& r1,
                                       uint32_t& r2, uint32_t& r3, uint32_t addr) {
    asm volatile("ldmatrix.sync.aligned.m8n8.x4.trans.shared.b16 {%0,%1,%2,%3}, [%4];"
                 : "=r"(r0), "=r"(r1), "=r"(r2), "=r"(r3) : "r"(addr));
}
__device__ __forceinline__ void mma16816(float* d, const uint32_t* a, const uint32_t* b) {
    asm volatile("mma.sync.aligned.m16n8k16.row.col.f32.f16.f16.f32 "
        "{%0,%1,%2,%3}, {%4,%5,%6,%7}, {%8,%9}, {%0,%1,%2,%3};"
        : "+f"(d[0]), "+f"(d[1]), "+f"(d[2]), "+f"(d[3])
        : "r"(a[0]), "r"(a[1]), "r"(a[2]), "r"(a[3]), "r"(b[0]), "r"(b[1]));
}
__device__ __forceinline__ void split2(float v, __half& h, __half& l) {
    h = __float2half(v);
    l = __float2half(v - __half2float(h));
}
__device__ __forceinline__ uint32_t pack2(float a, float b) {
    __half2 hp = __halves2half2(__float2half(a), __float2half(b));
    return *(uint32_t*)&hp;
}
__device__ __forceinline__ uint32_t pack2h(__half a, __half b) {
    __half2 hp = __halves2half2(a, b);
    return *(uint32_t*)&hp;
}

// ---------------------------------------------------------------------------
// HMMA GEMM (as R7): C[M,N] (+)= (Ah+Al)[M,K] * B^T, B stored [N,K] fp16.
// CTA 128x128, 128 threads (4 warps 2x2, 64x64 tiles), KC=32, 3 stages,
// 90KB smem -> 2 CTAs/SM.
// ---------------------------------------------------------------------------
#define STAGES  3
#define KC      32
#define PITCH   80u
#define A_TILE  (128u * PITCH)
#define STAGE_B (3u * A_TILE)
#define SMEM_B  (STAGES * STAGE_B)     // 92160

template<bool BIAS, bool RELU, bool ACCUM, bool SPLIT>
__global__ __launch_bounds__(128, 2)
void gemm_mma(const __half* __restrict__ Ah, const __half* __restrict__ Al,
              const __half* __restrict__ Bh,
              const float* __restrict__ bias,
              float* __restrict__ C,
              __half* __restrict__ Ch, __half* __restrict__ Cl,
              int M, int N, int K)
{
    extern __shared__ char smem_raw[];
    const uint32_t sb = smem_u32(smem_raw);

    const int tid  = threadIdx.x;
    const int wid  = tid >> 5;
    const int lane = tid & 31;
    const int row0 = blockIdx.x * 128;
    const int col0 = blockIdx.y * 128;
    const int NC   = K / KC;

    auto load_stage = [&](int s) {
        const uint32_t stg = sb + (uint32_t)(s % STAGES) * STAGE_B;
        const int k0 = s * KC;
        #pragma unroll
        for (int i = 0; i < 8; i++) {
            int f = i * 128 + tid;
            int sub = f >> 9;
            int rem = f & 511;
            int r = rem >> 2, c = rem & 3;
            const __half* src = ((sub == 0) ? Ah : Al)
                              + (size_t)(row0 + r) * K + k0 + c * 8;
            cp16(stg + (uint32_t)sub * A_TILE + (uint32_t)r * PITCH + c * 16, src);
        }
        #pragma unroll
        for (int i = 0; i < 4; i++) {
            int f = i * 128 + tid;
            int r = f >> 2, c = f & 3;
            const __half* src = Bh + (size_t)(col0 + r) * K + k0 + c * 8;
            cp16(stg + 2u*A_TILE + (uint32_t)r * PITCH + c * 16, src);
        }
        CP_COMMIT();
    };

    load_stage(0);
    if (NC > 1) load_stage(1);

    const int wm = wid >> 1;
    const int wn = wid & 1;

    float acc[4][8][4];
    #pragma unroll
    for (int a = 0; a < 4; a++)
        #pragma unroll
        for (int b = 0; b < 8; b++)
            #pragma unroll
            for (int c = 0; c < 4; c++) acc[a][b][c] = 0.f;

    for (int i = 0; i < NC; i++) {
        if (i < NC - 1) CP_WAIT1(); else CP_WAIT0();
        __syncthreads();
        if (i + 2 < NC) load_stage(i + 2);

        const uint32_t stg  = sb + (uint32_t)(i % STAGES) * STAGE_B;
        const uint32_t ah_b = stg;
        const uint32_t al_b = stg + A_TILE;
        const uint32_t bh_b = stg + 2u*A_TILE;

        #pragma unroll
        for (int ks = 0; ks < 2; ks++) {
            uint32_t ah[4][4], al[4][4], bf[8][2];
            const uint32_t a_coff = (uint32_t)ks * 32 + ((lane >> 4) << 4);
            #pragma unroll
            for (int mi = 0; mi < 4; mi++) {
                uint32_t r = (uint32_t)(wm * 64 + mi * 16 + (lane & 15));
                ldsm4(ah[mi][0], ah[mi][1], ah[mi][2], ah[mi][3], ah_b + r * PITCH + a_coff);
                ldsm4(al[mi][0], al[mi][1], al[mi][2], al[mi][3], al_b + r * PITCH + a_coff);
            }
            const uint32_t b_coff = (uint32_t)ks * 32 + (((lane >> 3) & 1) << 4);
            #pragma unroll
            for (int g = 0; g < 4; g++) {
                uint32_t r = (uint32_t)(wn * 64 + g * 16 + (lane & 7) + ((lane >> 4) << 3));
                ldsm4(bf[2*g][0], bf[2*g][1], bf[2*g+1][0], bf[2*g+1][1], bh_b + r * PITCH + b_coff);
            }
            #pragma unroll
            for (int mi = 0; mi < 4; mi++)
                #pragma unroll
                for (int ni = 0; ni < 8; ni++) {
                    mma16816(acc[mi][ni], ah[mi], bf[ni]);
                    mma16816(acc[mi][ni], al[mi], bf[ni]);
                }
        }
    }

    #pragma unroll
    for (int mi = 0; mi < 4; mi++) {
        #pragma unroll
        for (int rg = 0; rg < 2; rg++) {
            int r = row0 + wm * 64 + mi * 16 + (lane >> 2) + rg * 8;
            #pragma unroll
            for (int ni = 0; ni < 8; ni++) {
                int c = col0 + wn * 64 + ni * 8 + (lane & 3) * 2;
                float v0 = acc[mi][ni][rg * 2 + 0];
                float v1 = acc[mi][ni][rg * 2 + 1];
                if (BIAS)  { v0 += bias[c]; v1 += bias[c + 1]; }
                if (RELU)  { v0 = fmaxf(v0, 0.f); v1 = fmaxf(v1, 0.f); }
                if (ACCUM) {
                    float2 o = *(const float2*)&C[(size_t)r * N + c];
                    v0 += o.x; v1 += o.y;
                }
                if (SPLIT) {
                    __half h0, l0, h1, l1;
                    split2(v0, h0, l0); split2(v1, h1, l1);
                    *(__half2*)&Ch[(size_t)r * N + c] = __halves2half2(h0, h1);
                    *(__half2*)&Cl[(size_t)r * N + c] = __halves2half2(l0, l1);
                } else {
                    *(float2*)&C[(size_t)r * N + c] = make_float2(v0, v1);
                }
            }
        }
    }
}

// ---------------------------------------------------------------------------
// Tensor-core causal flash attention over split-fp16 qkv [M, 3072].
// CTA: 64 queries x one (b,h). 128 threads = 4 warps x 16 q rows.
// Scores: Qh*Kh + Ql*Kh + Qh*Kl (3 MMA). PV: Ph*Vh + Pl*Vh + Ph*Vl (3 MMA),
// V fragments via ldmatrix.trans. Online softmax in fp32 regs.
// 2-stage cp.async ping-pong of K/V hi/lo tiles.
// ---------------------------------------------------------------------------
#define AT_PITCH 144u                 // 64 halfs = 128B + 16 pad
#define AT_TILE  (64u * AT_PITCH)     // 9216
#define AT_STAGE (4u * AT_TILE)       // Kh | Kl | Vh | Vl = 36864
#define AT_SMEM  (2u * AT_STAGE)      // 73728

__global__ __launch_bounds__(128, 2)
void attn_mma(const __half* __restrict__ QKVh, const __half* __restrict__ QKVl,
              __half* __restrict__ Yh, __half* __restrict__ Yl)
{
    extern __shared__ char smem_raw[];
    const uint32_t sb = smem_u32(smem_raw);

    const int tid  = threadIdx.x;
    const int wid  = tid >> 5;
    const int lane = tid & 31;
    const int bh = blockIdx.y;
    const int b  = bh >> 4;
    const int h  = bh & 15;
    const int qt = (int)(gridDim.x - 1 - blockIdx.x);   // big tiles first
    const int qrow = b * TT + qt * 64;

    // K/V tile loader into stage st (Kh|Kl|Vh|Vl), tile index stile
    auto load_kv = [&](int st, int stile) {
        const uint32_t stg = sb + (uint32_t)st * AT_STAGE;
        const int srow = b * TT + stile * 64;
        #pragma unroll
        for (int i = 0; i < 16; i++) {
            int f = i * 128 + tid;            // 0..2047
            int sub = f >> 9;                 // 0:Kh 1:Kl 2:Vh 3:Vl
            int rem = f & 511;
            int r = rem >> 3, c = rem & 7;
            int colbase = ((sub < 2) ? DD : 2*DD) + h * 64;
            const __half* src = ((sub & 1) ? QKVl : QKVh)
                              + (size_t)(srow + r) * QKVD + colbase + c * 8;
            cp16(stg + (uint32_t)sub * AT_TILE + (uint32_t)r * AT_PITCH + c * 16, src);
        }
        CP_COMMIT();
    };

    // prologue: kv tile 0 -> stage 0; Q -> stage1 Kh/Kl slots
    load_kv(0, 0);
    {
        const uint32_t qstg = sb + AT_STAGE;
        #pragma unroll
        for (int i = 0; i < 8; i++) {
            int f = i * 128 + tid;            // 0..1023
            int sub = f >> 9;
            int rem = f & 511;
            int r = rem >> 3, c = rem & 7;
            const __half* src = (sub ? QKVl : QKVh)
                              + (size_t)(qrow + r) * QKVD + h * 64 + c * 8;
            cp16(qstg + (uint32_t)sub * AT_TILE + (uint32_t)r * AT_PITCH + c * 16, src);
        }
        CP_COMMIT();
    }
    CP_WAIT0();
    __syncthreads();

    // Q fragments (A operand, m16 x k16 per kstep)
    uint32_t qf_h[4][4], qf_l[4][4];
    {
        const uint32_t qstg = sb + AT_STAGE;
        uint32_t r = (uint32_t)(wid * 16 + (lane & 15));
        #pragma unroll
        for (int ks = 0; ks < 4; ks++) {
            uint32_t coff = (uint32_t)ks * 32 + ((lane >> 4) << 4);
            ldsm4(qf_h[ks][0], qf_h[ks][1], qf_h[ks][2], qf_h[ks][3],
                  qstg + r * AT_PITCH + coff);
            ldsm4(qf_l[ks][0], qf_l[ks][1], qf_l[ks][2], qf_l[ks][3],
                  qstg + AT_TILE + r * AT_PITCH + coff);
        }
    }
    __syncthreads();                 // done reading stage1 (Q staging)
    if (qt >= 1) load_kv(1, 1);

    float yacc[8][4];
    #pragma unroll
    for (int i = 0; i < 8; i++)
        #pragma unroll
        for (int j = 0; j < 4; j++) yacc[i][j] = 0.f;
    float m0 = -1e30f, m1 = -1e30f, l0 = 0.f, l1 = 0.f;

    for (int st = 0; st <= qt; st++) {
        if (st < qt) CP_WAIT1(); else CP_WAIT0();
        __syncthreads();
        const uint32_t stg = sb + (uint32_t)(st & 1) * AT_STAGE;

        // ---- scores S = Q K^T (3-term split) ----
        float sacc[8][4];
        #pragma unroll
        for (int i = 0; i < 8; i++)
            #pragma unroll
            for (int j = 0; j < 4; j++) sacc[i][j] = 0.f;

        const uint32_t kb_h = stg;
        const uint32_t kb_l = stg + AT_TILE;
        #pragma unroll
        for (int ks = 0; ks < 4; ks++) {
            const uint32_t coff = (uint32_t)ks * 32 + (((lane >> 3) & 1) << 4);
            #pragma unroll
            for (int nbp = 0; nbp < 4; nbp++) {
                uint32_t r = (uint32_t)(nbp * 16 + (lane & 7) + ((lane >> 4) << 3));
                uint32_t kh[4], kl[4];
                ldsm4(kh[0], kh[1], kh[2], kh[3], kb_h + r * AT_PITCH + coff);
                mma16816(sacc[2*nbp],   qf_h[ks], kh + 0);
                mma16816(sacc[2*nbp+1], qf_h[ks], kh + 2);
                mma16816(sacc[2*nbp],   qf_l[ks], kh + 0);
                mma16816(sacc[2*nbp+1], qf_l[ks], kh + 2);
                ldsm4(kl[0], kl[1], kl[2], kl[3], kb_l + r * AT_PITCH + coff);
                mma16816(sacc[2*nbp],   qf_h[ks], kl + 0);
                mma16816(sacc[2*nbp+1], qf_h[ks], kl + 2);
            }
        }

        // ---- softmax ----
        #pragma unroll
        for (int ni = 0; ni < 8; ni++)
            #pragma unroll
            for (int j = 0; j < 4; j++) sacc[ni][j] *= 0.125f;

        if (st == qt) {                     // diagonal tile: mask s>t
            int q0 = wid * 16 + (lane >> 2);
            #pragma unroll
            for (int ni = 0; ni < 8; ni++) {
                int s0c = ni * 8 + 2 * (lane & 3);
                if (s0c     > q0)     sacc[ni][0] = -1e30f;
                if (s0c + 1 > q0)     sacc[ni][1] = -1e30f;
                if (s0c     > q0 + 8) sacc[ni][2] = -1e30f;
                if (s0c + 1 > q0 + 8) sacc[ni][3] = -1e30f;
            }
        }

        float mx0 = -1e30f, mx1 = -1e30f;
        #pragma unroll
        for (int ni = 0; ni < 8; ni++) {
            mx0 = fmaxf(mx0, fmaxf(sacc[ni][0], sacc[ni][1]));
            mx1 = fmaxf(mx1, fmaxf(sacc[ni][2], sacc[ni][3]));
        }
        mx0 = fmaxf(mx0, __shfl_xor_sync(0xffffffffu, mx0, 1));
        mx0 = fmaxf(mx0, __shfl_xor_sync(0xffffffffu, mx0, 2));
        mx1 = fmaxf(mx1, __shfl_xor_sync(0xffffffffu, mx1, 1));
        mx1 = fmaxf(mx1, __shfl_xor_sync(0xffffffffu, mx1, 2));

        float mn0 = fmaxf(m0, mx0), mn1 = fmaxf(m1, mx1);
        float c0 = __expf(m0 - mn0), c1 = __expf(m1 - mn1);
        l0 *= c0; l1 *= c1;
        #pragma unroll
        for (int db = 0; db < 8; db++) {
            yacc[db][0] *= c0; yacc[db][1] *= c0;
            yacc[db][2] *= c1; yacc[db][3] *= c1;
        }

        uint32_t pf_h[4][4], pf_l[4][4];
        float s0 = 0.f, s1 = 0.f;
        #pragma unroll
        for (int ni = 0; ni < 8; ni++) {
            float p0 = __expf(sacc[ni][0] - mn0);
            float p1 = __expf(sacc[ni][1] - mn0);
            float p2 = __expf(sacc[ni][2] - mn1);
            float p3 = __expf(sacc[ni][3] - mn1);
            s0 += p0 + p1; s1 += p2 + p3;
            __half h0, lo0, h1, lo1, h2, lo2, h3, lo3;
            split2(p0, h0, lo0); split2(p1, h1, lo1);
            split2(p2, h2, lo2); split2(p3, h3, lo3);
            int ks = ni >> 1;
            if ((ni & 1) == 0) {
                pf_h[ks][0] = pack2h(h0, h1);  pf_h[ks][1] = pack2h(h2, h3);
                pf_l[ks][0] = pack2h(lo0, lo1); pf_l[ks][1] = pack2h(lo2, lo3);
            } else {
                pf_h[ks][2] = pack2h(h0, h1);  pf_h[ks][3] = pack2h(h2, h3);
                pf_l[ks][2] = pack2h(lo0, lo1); pf_l[ks][3] = pack2h(lo2, lo3);
            }
        }
        s0 += __shfl_xor_sync(0xffffffffu, s0, 1);
        s0 += __shfl_xor_sync(0xffffffffu, s0, 2);
        s1 += __shfl_xor_sync(0xffffffffu, s1, 1);
        s1 += __shfl_xor_sync(0xffffffffu, s1, 2);
        l0 += s0; l1 += s1;
        m0 = mn0; m1 = mn1;

        // ---- y += P V (3-term split), V via ldmatrix.trans ----
        const uint32_t vb_h = stg + 2u * AT_TILE;
        const uint32_t vb_l = stg + 3u * AT_TILE;
        #pragma unroll
        for (int ks = 0; ks < 4; ks++) {
            #pragma unroll
            for (int dbp = 0; dbp < 4; dbp++) {
                uint32_t raddr = (uint32_t)(ks * 16 + (lane & 15)) * AT_PITCH
                               + (uint32_t)dbp * 32 + ((lane >> 4) << 4);
                uint32_t vh[4], vl[4];
                ldsm4t(vh[0], vh[1], vh[2], vh[3], vb_h + raddr);
                mma16816(yacc[2*dbp],   pf_h[ks], vh + 0);
                mma16816(yacc[2*dbp+1], pf_h[ks], vh + 2);
                mma16816(yacc[2*dbp],   pf_l[ks], vh + 0);
                mma16816(yacc[2*dbp+1], pf_l[ks], vh + 2);
                ldsm4t(vl[0], vl[1], vl[2], vl[3], vb_l + raddr);
                mma16816(yacc[2*dbp],   pf_h[ks], vl + 0);
                mma16816(yacc[2*dbp+1], pf_h[ks], vl + 2);
            }
        }

        if (st + 2 <= qt) {
            __syncthreads();                 // all reads of stage (st&1) done
            load_kv(st & 1, st + 2);
        }
    }

    // ---- epilogue: y/l -> split fp16 ----
    float inv0 = 1.f / l0, inv1 = 1.f / l1;
    int r0g = qrow + wid * 16 + (lane >> 2);
    size_t base0 = (size_t)r0g * DD + h * 64;
    size_t base1 = base0 + (size_t)8 * DD;
    #pragma unroll
    for (int db = 0; db < 8; db++) {
        int cc = db * 8 + 2 * (lane & 3);
        __half h0, lo0, h1, lo1;
        split2(yacc[db][0] * inv0, h0, lo0);
        split2(yacc[db][1] * inv0, h1, lo1);
        *(__half2*)&Yh[base0 + cc] = __halves2half2(h0, h1);
        *(__half2*)&Yl[base0 + cc] = __halves2half2(lo0, lo1);
        split2(yacc[db][2] * inv1, h0, lo0);
        split2(yacc[db][3] * inv1, h1, lo1);
        *(__half2*)&Yh[base1 + cc] = __halves2half2(h0, h1);
        *(__half2*)&Yl[base1 + cc] = __halves2half2(lo0, lo1);
    }
}

// ---------------------------------------------------------------------------
// Fused embedding + positional encoding + LayerNorm(ln1, layer 0).
// ---------------------------------------------------------------------------
__global__ __launch_bounds__(256) void embed_ln_kernel(const int* __restrict__ tokens,
                                                       const float* __restrict__ emb,
                                                       const float* __restrict__ w,
                                                       const float* __restrict__ b,
                                                       float* __restrict__ x,
                                                       __half* __restrict__ yh,
                                                       __half* __restrict__ yl)
{
    __shared__ float red[8];
    int row = blockIdx.x;
    int tid = threadIdx.x;
    int bb  = row >> 11;
    int t   = row & (TT - 1);
    int tok = (t == 0) ? 0 : tokens[bb * TT + t - 1];

    int c = tid * 4;
    float v[4];
    #pragma unroll
    for (int j = 0; j < 4; j++) {
        int d = c + j;
        int k = d & 1;
        double e = (double)(d - k) / (double)DD;
        float freq = (float)exp(-e * 11.512925464970229);   // LEN_MAX^-e
        float arg = (float)t * freq + 1.5707963267948966f * (float)k;
        v[j] = emb[(size_t)tok * DD + d] + sinf(arg);
    }
    *(float4*)&x[(size_t)row * DD + c] = make_float4(v[0], v[1], v[2], v[3]);

    float s = v[0] + v[1] + v[2] + v[3];
    #pragma unroll
    for (int o = 16; o > 0; o >>= 1) s += __shfl_xor_sync(0xffffffffu, s, o);
    if ((tid & 31) == 0) red[tid >> 5] = s;
    __syncthreads();
    float tot = 0.f;
    #pragma unroll
    for (int i = 0; i < 8; i++) tot += red[i];
    float mean = tot * (1.0f / DD);
    __syncthreads();

    float dx0 = v[0]-mean, dx1 = v[1]-mean, dx2 = v[2]-mean, dx3 = v[3]-mean;
    float s2 = dx0*dx0 + dx1*dx1 + dx2*dx2 + dx3*dx3;
    #pragma unroll
    for (int o = 16; o > 0; o >>= 1) s2 += __shfl_xor_sync(0xffffffffu, s2, o);
    if ((tid & 31) == 0) red[tid >> 5] = s2;
    __syncthreads();
    float tot2 = 0.f;
    #pragma unroll
    for (int i = 0; i < 8; i++) tot2 += red[i];
    float inv = rsqrtf(tot2 * (1.0f / DD) + 1e-5f);

    float4 wv = *(const float4*)&w[c];
    float4 bv = *(const float4*)&b[c];
    float o0 = dx0 * inv * wv.x + bv.x;
    float o1 = dx1 * inv * wv.y + bv.y;
    float o2 = dx2 * inv * wv.z + bv.z;
    float o3 = dx3 * inv * wv.w + bv.w;
    __half h0, l0, h1, l1, h2, l2, h3, l3;
    split2(o0, h0, l0); split2(o1, h1, l1); split2(o2, h2, l2); split2(o3, h3, l3);
    size_t off = (size_t)row * DD + c;
    *(__half2*)&yh[off]     = __halves2half2(h0, h1);
    *(__half2*)&yh[off + 2] = __halves2half2(h2, h3);
    *(__half2*)&yl[off]     = __halves2half2(l0, l1);
    *(__half2*)&yl[off + 2] = __halves2half2(l2, l3);
}

// ---------------------------------------------------------------------------
// LayerNorm -> split fp16 hi/lo output
// ---------------------------------------------------------------------------
__global__ __launch_bounds__(256) void ln_split_kernel(const float* __restrict__ x,
                                                       __half* __restrict__ yh,
                                                       __half* __restrict__ yl,
                                                       const float* __restrict__ w,
                                                       const float* __restrict__ b)
{
    __shared__ float red[8];
    int row = blockIdx.x;
    int tid = threadIdx.x;
    const float* xr = x + (size_t)row * DD;
    float4 xv = *(const float4*)&xr[tid * 4];

    float s = xv.x + xv.y + xv.z + xv.w;
    #pragma unroll
    for (int o = 16; o > 0; o >>= 1) s += __shfl_xor_sync(0xffffffffu, s, o);
    if ((tid & 31) == 0) red[tid >> 5] = s;
    __syncthreads();
    float tot = 0.f;
    #pragma unroll
    for (int i = 0; i < 8; i++) tot += red[i];
    float mean = tot * (1.0f / DD);
    __syncthreads();

    float dx0 = xv.x - mean, dx1 = xv.y - mean, dx2 = xv.z - mean, dx3 = xv.w - mean;
    float s2 = dx0*dx0 + dx1*dx1 + dx2*dx2 + dx3*dx3;
    #pragma unroll
    for (int o = 16; o > 0; o >>= 1) s2 += __shfl_xor_sync(0xffffffffu, s2, o);
    if ((tid & 31) == 0) red[tid >> 5] = s2;
    __syncthreads();
    float tot2 = 0.f;
    #pragma unroll
    for (int i = 0; i < 8; i++) tot2 += red[i];
    float inv = rsqrtf(tot2 * (1.0f / DD) + 1e-5f);

    int c = tid * 4;
    float4 wv = *(const float4*)&w[c];
    float4 bv = *(const float4*)&b[c];
    float o0 = dx0 * inv * wv.x + bv.x;
    float o1 = dx1 * inv * wv.y + bv.y;
    float o2 = dx2 * inv * wv.z + bv.z;
    float o3 = dx3 * inv * wv.w + bv.w;
    __half h0, l0, h1, l1, h2, l2, h3, l3;
    split2(o0, h0, l0); split2(o1, h1, l1); split2(o2, h2, l2); split2(o3, h3, l3);
    size_t off = (size_t)row * DD + c;
    *(__half2*)&yh[off]     = __halves2half2(h0, h1);
    *(__half2*)&yh[off + 2] = __halves2half2(h2, h3);
    *(__half2*)&yl[off]     = __halves2half2(l0, l1);
    *(__half2*)&yl[off + 2] = __halves2half2(l2, l3);
}

// ---------------------------------------------------------------------------
// Weight conversion kernels (single fp16, vectorized x4)
// ---------------------------------------------------------------------------
__global__ void conv_kernel(const float* __restrict__ s,
                            __half* __restrict__ h, int n4)
{
    int i = blockIdx.x * blockDim.x + threadIdx.x;
    if (i >= n4) return;
    float4 v = *(const float4*)&s[i * 4];
    *(__half2*)&h[i*4]   = __halves2half2(__float2half(v.x), __float2half(v.y));
    *(__half2*)&h[i*4+2] = __halves2half2(__float2half(v.z), __float2half(v.w));
}

__global__ void pack_qkv_kernel(const float* __restrict__ wq,
                                const float* __restrict__ wk,
                                const float* __restrict__ wv,
                                __half* __restrict__ h)
{
    int i = blockIdx.x * blockDim.x + threadIdx.x;
    const int per_layer4 = QKVD * DD / 4;
    if (i >= LL * per_layer4) return;
    int lyr = i / per_layer4;
    int rem = i - lyr * per_layer4;
    int row = rem >> 8;
    int c4  = rem & 255;
    int which = row >> 10;
    int srow  = row & 1023;
    const float* src = (which == 0) ? wq : ((which == 1) ? wk : wv);
    float4 v = *(const float4*)&src[(size_t)lyr * (DD*DD) + (size_t)srow * DD + c4 * 4];
    size_t o = (size_t)i * 4;
    *(__half2*)&h[o]   = __halves2half2(__float2half(v.x), __float2half(v.y));
    *(__half2*)&h[o+2] = __halves2half2(__float2half(v.z), __float2half(v.w));
}

__global__ void transpose_wo_kernel(const float* __restrict__ wo,
                                    __half* __restrict__ h)
{
    int i = blockIdx.x * blockDim.x + threadIdx.x;
    if (i >= LL * DD * DD) return;
    int lyr = i >> 20;
    int rem = i & ((1 << 20) - 1);
    int nrow = rem >> 10;
    int kcol = rem & 1023;
    h[i] = __float2half(wo[((size_t)lyr << 20) + ((size_t)kcol << 10) + nrow]);
}

// ---------------------------------------------------------------------------
// Launch
// ---------------------------------------------------------------------------
extern "C" void kernel_launch(void* const* d_in, const int* in_sizes, int n_in,
                              void* d_out, int out_size)
{
    const int*   tokens = (const int*)  d_in[0];
    const float* emb    = (const float*)d_in[1];
    const float* ln1_w  = (const float*)d_in[2];
    const float* ln1_b  = (const float*)d_in[3];
    const float* w_q    = (const float*)d_in[4];
    const float* w_k    = (const float*)d_in[5];
    const float* w_v    = (const float*)d_in[6];
    const float* w_o    = (const float*)d_in[7];
    const float* ln2_w  = (const float*)d_in[8];
    const float* ln2_b  = (const float*)d_in[9];
    const float* w1     = (const float*)d_in[10];
    const float* b1     = (const float*)d_in[11];
    const float* w2     = (const float*)d_in[12];
    const float* b2     = (const float*)d_in[13];
    const float* ro_w   = (const float*)d_in[14];
    const float* ro_b   = (const float*)d_in[15];
    float* out = (float*)d_out;

    float *x;
    __half *qkvh, *qkvl, *xnh, *xnl, *yh, *yl, *hh, *hl, *xh, *xl;
    __half *wqkv, *wo, *w1w, *w2w, *ro;
    cudaGetSymbolAddress((void**)&x,    g_x);
    cudaGetSymbolAddress((void**)&qkvh, g_qkvh); cudaGetSymbolAddress((void**)&qkvl, g_qkvl);
    cudaGetSymbolAddress((void**)&xnh,  g_xnh);  cudaGetSymbolAddress((void**)&xnl, g_xnl);
    cudaGetSymbolAddress((void**)&yh,   g_yh);   cudaGetSymbolAddress((void**)&yl,  g_yl);
    cudaGetSymbolAddress((void**)&hh,   g_hh);   cudaGetSymbolAddress((void**)&hl,  g_hl);
    cudaGetSymbolAddress((void**)&xh,   g_xh);   cudaGetSymbolAddress((void**)&xl,  g_xl);
    cudaGetSymbolAddress((void**)&wqkv, g_wqkv);
    cudaGetSymbolAddress((void**)&wo,   g_wo);
    cudaGetSymbolAddress((void**)&w1w,  g_w1);
    cudaGetSymbolAddress((void**)&w2w,  g_w2);
    cudaGetSymbolAddress((void**)&ro,   g_ro);

    cudaFuncSetAttribute((const void*)gemm_mma<false,false,false,true>,
                         cudaFuncAttributeMaxDynamicSharedMemorySize, SMEM_B);
    cudaFuncSetAttribute((const void*)gemm_mma<false,false,true,false>,
                         cudaFuncAttributeMaxDynamicSharedMemorySize, SMEM_B);
    cudaFuncSetAttribute((const void*)gemm_mma<true,true,false,true>,
                         cudaFuncAttributeMaxDynamicSharedMemorySize, SMEM_B);
    cudaFuncSetAttribute((const void*)gemm_mma<true,false,true,false>,
                         cudaFuncAttributeMaxDynamicSharedMemorySize, SMEM_B);
    cudaFuncSetAttribute((const void*)gemm_mma<true,false,true,true>,
                         cudaFuncAttributeMaxDynamicSharedMemorySize, SMEM_B);
    cudaFuncSetAttribute((const void*)gemm_mma<true,false,false,false>,
                         cudaFuncAttributeMaxDynamicSharedMemorySize, SMEM_B);
    cudaFuncSetAttribute((const void*)attn_mma,
                         cudaFuncAttributeMaxDynamicSharedMemorySize, AT_SMEM);

    // grid: x = M-block (fast), y = N-block (slow)
    const dim3 gQKV(MM/128, QKVD/128);    // 32 x 24
    const dim3 gD  (MM/128, DD/128);      // 32 x 8
    const dim3 gH  (MM/128, HDIM/128);    // 32 x 32
    const dim3 gV  (MM/128, VV/128);      // 32 x 250
    const dim3 gA  (TT/64, BB*HH);        // 32 x 32

    pack_qkv_kernel<<<(LL*QKVD*DD/4 + 255)/256, 256>>>(w_q, w_k, w_v, wqkv);
    embed_ln_kernel<<<MM, 256>>>(tokens, emb, ln1_w, ln1_b, x, xnh, xnl);
    transpose_wo_kernel<<<(LL*DD*DD + 255)/256, 256>>>(w_o, wo);
    gemm_mma<false,false,false,true><<<gQKV, 128, SMEM_B>>>(
        xnh, xnl, wqkv, nullptr, nullptr, qkvh, qkvl, MM, QKVD, DD);
    conv_kernel<<<(LL*HDIM*DD/4 + 255)/256, 256>>>(w1, w1w, LL*HDIM*DD/4);
    conv_kernel<<<(LL*DD*HDIM/4 + 255)/256, 256>>>(w2, w2w, LL*DD*HDIM/4);
    conv_kernel<<<(VV*DD/4 + 255)/256, 256>>>(ro_w, ro, VV*DD/4);

    for (int l = 0; l < LL; l++) {
        const __half* wqkv_l = wqkv + (size_t)l * QKVD * DD;
        const __half* wo_l   = wo   + (size_t)l * DD * DD;
        const __half* w1_l   = w1w  + (size_t)l * HDIM * DD;
        const __half* w2_l   = w2w  + (size_t)l * DD * HDIM;

        if (l > 0) {
            ln_split_kernel<<<MM, 256>>>(x, xnh, xnl, ln1_w + (size_t)l*DD, ln1_b + (size_t)l*DD);
            gemm_mma<false,false,false,true><<<gQKV, 128, SMEM_B>>>(
                xnh, xnl, wqkv_l, nullptr, nullptr, qkvh, qkvl, MM, QKVD, DD);
        }

        attn_mma<<<gA, 128, AT_SMEM>>>(qkvh, qkvl, yh, yl);

        gemm_mma<false,false,true,false><<<gD, 128, SMEM_B>>>(
            yh, yl, wo_l, nullptr, x, nullptr, nullptr, MM, DD, DD);

        ln_split_kernel<<<MM, 256>>>(x, xnh, xnl, ln2_w + (size_t)l*DD, ln2_b + (size_t)l*DD);

        gemm_mma<true,true,false,true><<<gH, 128, SMEM_B>>>(
            xnh, xnl, w1_l, b1 + (size_t)l*HDIM, nullptr, hh, hl, MM, HDIM, DD);

        if (l < LL - 1) {
            gemm_mma<true,false,true,false><<<gD, 128, SMEM_B>>>(
                hh, hl, w2_l, b2 + (size_t)l*DD, x, nullptr, nullptr, MM, DD, HDIM);
        } else {
            gemm_mma<true,false,true,true><<<gD, 128, SMEM_B>>>(
                hh, hl, w2_l, b2 + (size_t)l*DD, x, xh, xl, MM, DD, HDIM);
        }
    }

    gemm_mma<true,false,false,false><<<gV, 128, SMEM_B>>>(
        xh, xl, ro, ro_b, out, nullptr, nullptr, MM, VV, DD);
}

// round 9
// speedup vs baseline: 1.8486x; 1.1608x over previous
#include <cuda_runtime.h>
#include <cuda_fp16.h>
#include <math.h>
#include <stdint.h>

// ---------------------------------------------------------------------------
// Problem constants
// ---------------------------------------------------------------------------
#define BB   2
#define TT   2048
#define DD   1024
#define HH   16
#define HDIM 4096
#define VV   32000
#define LL   4
#define MM   (BB*TT)      // 4096 rows
#define QKVD (3*DD)       // 3072

// ---------------------------------------------------------------------------
// Static device scratch (no allocations allowed)
// ---------------------------------------------------------------------------
__device__ float g_x  [MM*DD];
__device__ __half g_qkvh[MM*QKVD], g_qkvl[MM*QKVD];
__device__ __half g_xnh[MM*DD],  g_xnl[MM*DD];
__device__ __half g_yh [MM*DD],  g_yl [MM*DD];
__device__ __half g_hh [MM*HDIM], g_hl [MM*HDIM];
__device__ __half g_xh [MM*DD],  g_xl [MM*DD];
// single-term fp16 weights (recomputed every launch — weights are inputs)
__device__ __half g_wqkv[LL*QKVD*DD];
__device__ __half g_wo  [LL*DD*DD];
__device__ __half g_w1  [LL*HDIM*DD];
__device__ __half g_w2  [LL*DD*HDIM];
__device__ __half g_ro  [VV*DD];

// ---------------------------------------------------------------------------
// helpers (base-target PTX only: cp.async, ldmatrix, mma.sync)
// ---------------------------------------------------------------------------
__device__ __forceinline__ uint32_t smem_u32(const void* p) {
    uint32_t a;
    asm("{ .reg .u64 t; cvta.to.shared.u64 t, %1; cvt.u32.u64 %0, t; }"
        : "=r"(a) : "l"(p));
    return a;
}
__device__ __forceinline__ void cp16(uint32_t dst, const void* src) {
    asm volatile("cp.async.cg.shared.global [%0], [%1], 16;" :: "r"(dst), "l"(src));
}
#define CP_COMMIT()  asm volatile("cp.async.commit_group;" ::: "memory")
#define CP_WAIT0()   asm volatile("cp.async.wait_group 0;" ::: "memory")
#define CP_WAIT1()   asm volatile("cp.async.wait_group 1;" ::: "memory")

__device__ __forceinline__ void ldsm4(uint32_t& r0, uint32_t& r1,
                                      uint32_t& r2, uint32_t& r3, uint32_t addr) {
    asm volatile("ldmatrix.sync.aligned.m8n8.x4.shared.b16 {%0,%1,%2,%3}, [%4];"
                 : "=r"(r0), "=r"(r1), "=r"(r2), "=r"(r3) : "r"(addr));
}
__device__ __forceinline__ void ldsm4t(uint32_t& r0, uint32_t& r1,
                                       uint32_t& r2, uint32_t& r3, uint32_t addr) {
    asm volatile("ldmatrix.sync.aligned.m8n8.x4.trans.shared.b16 {%0,%1,%2,%3}, [%4];"
                 : "=r"(r0), "=r"(r1), "=r"(r2), "=r"(r3) : "r"(addr));
}
__device__ __forceinline__ void mma16816(float* d, const uint32_t* a, const uint32_t* b) {
    asm volatile("mma.sync.aligned.m16n8k16.row.col.f32.f16.f16.f32 "
        "{%0,%1,%2,%3}, {%4,%5,%6,%7}, {%8,%9}, {%0,%1,%2,%3};"
        : "+f"(d[0]), "+f"(d[1]), "+f"(d[2]), "+f"(d[3])
        : "r"(a[0]), "r"(a[1]), "r"(a[2]), "r"(a[3]), "r"(b[0]), "r"(b[1]));
}
__device__ __forceinline__ void split2(float v, __half& h, __half& l) {
    h = __float2half(v);
    l = __float2half(v - __half2float(h));
}
__device__ __forceinline__ uint32_t pack2h(__half a, __half b) {
    __half2 hp = __halves2half2(a, b);
    return *(uint32_t*)&hp;
}

// ---------------------------------------------------------------------------
// HMMA GEMM: C[M,N] (+)= A[M,K] * B^T, B stored [N,K] fp16.
// TWOA=1: A = Ah + Al (2-term split, 2 MMA per k16).
// TWOA=0: A = Ah only (1 MMA per k16) — used for the readout, where A-quant
//         error cannot be amplified by later layers.
// CTA 128x128, 128 threads (4 warps 2x2, 64x64 tiles), KC=32, 3 stages,
// 90KB smem -> 2 CTAs/SM.
// ---------------------------------------------------------------------------
#define STAGES  3
#define KC      32
#define PITCH   80u
#define A_TILE  (128u * PITCH)
#define STAGE_B (3u * A_TILE)
#define SMEM_B  (STAGES * STAGE_B)     // 92160

template<bool BIAS, bool RELU, bool ACCUM, bool SPLIT, bool TWOA>
__global__ __launch_bounds__(128, 2)
void gemm_mma(const __half* __restrict__ Ah, const __half* __restrict__ Al,
              const __half* __restrict__ Bh,
              const float* __restrict__ bias,
              float* __restrict__ C,
              __half* __restrict__ Ch, __half* __restrict__ Cl,
              int M, int N, int K)
{
    extern __shared__ char smem_raw[];
    const uint32_t sb = smem_u32(smem_raw);

    const int tid  = threadIdx.x;
    const int wid  = tid >> 5;
    const int lane = tid & 31;
    const int row0 = blockIdx.x * 128;
    const int col0 = blockIdx.y * 128;
    const int NC   = K / KC;

    auto load_stage = [&](int s) {
        const uint32_t stg = sb + (uint32_t)(s % STAGES) * STAGE_B;
        const int k0 = s * KC;
        const int a_iters = TWOA ? 8 : 4;
        #pragma unroll
        for (int i = 0; i < 8; i++) {
            if (i >= a_iters) break;
            int f = i * 128 + tid;
            int sub = f >> 9;                 // 0:Ah 1:Al
            int rem = f & 511;
            int r = rem >> 2, c = rem & 3;
            const __half* src = ((sub == 0) ? Ah : Al)
                              + (size_t)(row0 + r) * K + k0 + c * 8;
            cp16(stg + (uint32_t)sub * A_TILE + (uint32_t)r * PITCH + c * 16, src);
        }
        #pragma unroll
        for (int i = 0; i < 4; i++) {
            int f = i * 128 + tid;
            int r = f >> 2, c = f & 3;
            const __half* src = Bh + (size_t)(col0 + r) * K + k0 + c * 8;
            cp16(stg + 2u*A_TILE + (uint32_t)r * PITCH + c * 16, src);
        }
        CP_COMMIT();
    };

    load_stage(0);
    if (NC > 1) load_stage(1);

    const int wm = wid >> 1;
    const int wn = wid & 1;

    float acc[4][8][4];
    #pragma unroll
    for (int a = 0; a < 4; a++)
        #pragma unroll
        for (int b = 0; b < 8; b++)
            #pragma unroll
            for (int c = 0; c < 4; c++) acc[a][b][c] = 0.f;

    for (int i = 0; i < NC; i++) {
        if (i < NC - 1) CP_WAIT1(); else CP_WAIT0();
        __syncthreads();
        if (i + 2 < NC) load_stage(i + 2);

        const uint32_t stg  = sb + (uint32_t)(i % STAGES) * STAGE_B;
        const uint32_t ah_b = stg;
        const uint32_t al_b = stg + A_TILE;
        const uint32_t bh_b = stg + 2u*A_TILE;

        #pragma unroll
        for (int ks = 0; ks < 2; ks++) {
            uint32_t ah[4][4], al[4][4], bf[8][2];
            const uint32_t a_coff = (uint32_t)ks * 32 + ((lane >> 4) << 4);
            #pragma unroll
            for (int mi = 0; mi < 4; mi++) {
                uint32_t r = (uint32_t)(wm * 64 + mi * 16 + (lane & 15));
                ldsm4(ah[mi][0], ah[mi][1], ah[mi][2], ah[mi][3], ah_b + r * PITCH + a_coff);
                if (TWOA)
                    ldsm4(al[mi][0], al[mi][1], al[mi][2], al[mi][3], al_b + r * PITCH + a_coff);
            }
            const uint32_t b_coff = (uint32_t)ks * 32 + (((lane >> 3) & 1) << 4);
            #pragma unroll
            for (int g = 0; g < 4; g++) {
                uint32_t r = (uint32_t)(wn * 64 + g * 16 + (lane & 7) + ((lane >> 4) << 3));
                ldsm4(bf[2*g][0], bf[2*g][1], bf[2*g+1][0], bf[2*g+1][1], bh_b + r * PITCH + b_coff);
            }
            #pragma unroll
            for (int mi = 0; mi < 4; mi++)
                #pragma unroll
                for (int ni = 0; ni < 8; ni++) {
                    mma16816(acc[mi][ni], ah[mi], bf[ni]);
                    if (TWOA) mma16816(acc[mi][ni], al[mi], bf[ni]);
                }
        }
    }

    #pragma unroll
    for (int mi = 0; mi < 4; mi++) {
        #pragma unroll
        for (int rg = 0; rg < 2; rg++) {
            int r = row0 + wm * 64 + mi * 16 + (lane >> 2) + rg * 8;
            #pragma unroll
            for (int ni = 0; ni < 8; ni++) {
                int c = col0 + wn * 64 + ni * 8 + (lane & 3) * 2;
                float v0 = acc[mi][ni][rg * 2 + 0];
                float v1 = acc[mi][ni][rg * 2 + 1];
                if (BIAS)  { v0 += bias[c]; v1 += bias[c + 1]; }
                if (RELU)  { v0 = fmaxf(v0, 0.f); v1 = fmaxf(v1, 0.f); }
                if (ACCUM) {
                    float2 o = *(const float2*)&C[(size_t)r * N + c];
                    v0 += o.x; v1 += o.y;
                }
                if (SPLIT) {
                    __half h0, l0, h1, l1;
                    split2(v0, h0, l0); split2(v1, h1, l1);
                    *(__half2*)&Ch[(size_t)r * N + c] = __halves2half2(h0, h1);
                    *(__half2*)&Cl[(size_t)r * N + c] = __halves2half2(l0, l1);
                } else {
                    *(float2*)&C[(size_t)r * N + c] = make_float2(v0, v1);
                }
            }
        }
    }
}

// ---------------------------------------------------------------------------
// Tensor-core causal flash attention over split-fp16 qkv [M, 3072].
// CTA: 64 queries x one (b,h). 128 threads = 4 warps x 16 q rows.
// Scores: Qh*Kh + Ql*Kh + Qh*Kl (3 MMA). PV: Ph*Vh + Pl*Vh + Ph*Vl (3 MMA).
// ---------------------------------------------------------------------------
#define AT_PITCH 144u
#define AT_TILE  (64u * AT_PITCH)
#define AT_STAGE (4u * AT_TILE)
#define AT_SMEM  (2u * AT_STAGE)      // 73728

__global__ __launch_bounds__(128, 2)
void attn_mma(const __half* __restrict__ QKVh, const __half* __restrict__ QKVl,
              __half* __restrict__ Yh, __half* __restrict__ Yl)
{
    extern __shared__ char smem_raw[];
    const uint32_t sb = smem_u32(smem_raw);

    const int tid  = threadIdx.x;
    const int wid  = tid >> 5;
    const int lane = tid & 31;
    const int bh = blockIdx.y;
    const int b  = bh >> 4;
    const int h  = bh & 15;
    const int qt = (int)(gridDim.x - 1 - blockIdx.x);
    const int qrow = b * TT + qt * 64;

    auto load_kv = [&](int st, int stile) {
        const uint32_t stg = sb + (uint32_t)st * AT_STAGE;
        const int srow = b * TT + stile * 64;
        #pragma unroll
        for (int i = 0; i < 16; i++) {
            int f = i * 128 + tid;
            int sub = f >> 9;
            int rem = f & 511;
            int r = rem >> 3, c = rem & 7;
            int colbase = ((sub < 2) ? DD : 2*DD) + h * 64;
            const __half* src = ((sub & 1) ? QKVl : QKVh)
                              + (size_t)(srow + r) * QKVD + colbase + c * 8;
            cp16(stg + (uint32_t)sub * AT_TILE + (uint32_t)r * AT_PITCH + c * 16, src);
        }
        CP_COMMIT();
    };

    load_kv(0, 0);
    {
        const uint32_t qstg = sb + AT_STAGE;
        #pragma unroll
        for (int i = 0; i < 8; i++) {
            int f = i * 128 + tid;
            int sub = f >> 9;
            int rem = f & 511;
            int r = rem >> 3, c = rem & 7;
            const __half* src = (sub ? QKVl : QKVh)
                              + (size_t)(qrow + r) * QKVD + h * 64 + c * 8;
            cp16(qstg + (uint32_t)sub * AT_TILE + (uint32_t)r * AT_PITCH + c * 16, src);
        }
        CP_COMMIT();
    }
    CP_WAIT0();
    __syncthreads();

    uint32_t qf_h[4][4], qf_l[4][4];
    {
        const uint32_t qstg = sb + AT_STAGE;
        uint32_t r = (uint32_t)(wid * 16 + (lane & 15));
        #pragma unroll
        for (int ks = 0; ks < 4; ks++) {
            uint32_t coff = (uint32_t)ks * 32 + ((lane >> 4) << 4);
            ldsm4(qf_h[ks][0], qf_h[ks][1], qf_h[ks][2], qf_h[ks][3],
                  qstg + r * AT_PITCH + coff);
            ldsm4(qf_l[ks][0], qf_l[ks][1], qf_l[ks][2], qf_l[ks][3],
                  qstg + AT_TILE + r * AT_PITCH + coff);
        }
    }
    __syncthreads();
    if (qt >= 1) load_kv(1, 1);

    float yacc[8][4];
    #pragma unroll
    for (int i = 0; i < 8; i++)
        #pragma unroll
        for (int j = 0; j < 4; j++) yacc[i][j] = 0.f;
    float m0 = -1e30f, m1 = -1e30f, l0 = 0.f, l1 = 0.f;

    for (int st = 0; st <= qt; st++) {
        if (st < qt) CP_WAIT1(); else CP_WAIT0();
        __syncthreads();
        const uint32_t stg = sb + (uint32_t)(st & 1) * AT_STAGE;

        float sacc[8][4];
        #pragma unroll
        for (int i = 0; i < 8; i++)
            #pragma unroll
            for (int j = 0; j < 4; j++) sacc[i][j] = 0.f;

        const uint32_t kb_h = stg;
        const uint32_t kb_l = stg + AT_TILE;
        #pragma unroll
        for (int ks = 0; ks < 4; ks++) {
            const uint32_t coff = (uint32_t)ks * 32 + (((lane >> 3) & 1) << 4);
            #pragma unroll
            for (int nbp = 0; nbp < 4; nbp++) {
                uint32_t r = (uint32_t)(nbp * 16 + (lane & 7) + ((lane >> 4) << 3));
                uint32_t kh[4], kl[4];
                ldsm4(kh[0], kh[1], kh[2], kh[3], kb_h + r * AT_PITCH + coff);
                mma16816(sacc[2*nbp],   qf_h[ks], kh + 0);
                mma16816(sacc[2*nbp+1], qf_h[ks], kh + 2);
                mma16816(sacc[2*nbp],   qf_l[ks], kh + 0);
                mma16816(sacc[2*nbp+1], qf_l[ks], kh + 2);
                ldsm4(kl[0], kl[1], kl[2], kl[3], kb_l + r * AT_PITCH + coff);
                mma16816(sacc[2*nbp],   qf_h[ks], kl + 0);
                mma16816(sacc[2*nbp+1], qf_h[ks], kl + 2);
            }
        }

        #pragma unroll
        for (int ni = 0; ni < 8; ni++)
            #pragma unroll
            for (int j = 0; j < 4; j++) sacc[ni][j] *= 0.125f;

        if (st == qt) {
            int q0 = wid * 16 + (lane >> 2);
            #pragma unroll
            for (int ni = 0; ni < 8; ni++) {
                int s0c = ni * 8 + 2 * (lane & 3);
                if (s0c     > q0)     sacc[ni][0] = -1e30f;
                if (s0c + 1 > q0)     sacc[ni][1] = -1e30f;
                if (s0c     > q0 + 8) sacc[ni][2] = -1e30f;
                if (s0c + 1 > q0 + 8) sacc[ni][3] = -1e30f;
            }
        }

        float mx0 = -1e30f, mx1 = -1e30f;
        #pragma unroll
        for (int ni = 0; ni < 8; ni++) {
            mx0 = fmaxf(mx0, fmaxf(sacc[ni][0], sacc[ni][1]));
            mx1 = fmaxf(mx1, fmaxf(sacc[ni][2], sacc[ni][3]));
        }
        mx0 = fmaxf(mx0, __shfl_xor_sync(0xffffffffu, mx0, 1));
        mx0 = fmaxf(mx0, __shfl_xor_sync(0xffffffffu, mx0, 2));
        mx1 = fmaxf(mx1, __shfl_xor_sync(0xffffffffu, mx1, 1));
        mx1 = fmaxf(mx1, __shfl_xor_sync(0xffffffffu, mx1, 2));

        float mn0 = fmaxf(m0, mx0), mn1 = fmaxf(m1, mx1);
        float c0 = __expf(m0 - mn0), c1 = __expf(m1 - mn1);
        l0 *= c0; l1 *= c1;
        #pragma unroll
        for (int db = 0; db < 8; db++) {
            yacc[db][0] *= c0; yacc[db][1] *= c0;
            yacc[db][2] *= c1; yacc[db][3] *= c1;
        }

        uint32_t pf_h[4][4], pf_l[4][4];
        float s0 = 0.f, s1 = 0.f;
        #pragma unroll
        for (int ni = 0; ni < 8; ni++) {
            float p0 = __expf(sacc[ni][0] - mn0);
            float p1 = __expf(sacc[ni][1] - mn0);
            float p2 = __expf(sacc[ni][2] - mn1);
            float p3 = __expf(sacc[ni][3] - mn1);
            s0 += p0 + p1; s1 += p2 + p3;
            __half h0, lo0, h1, lo1, h2, lo2, h3, lo3;
            split2(p0, h0, lo0); split2(p1, h1, lo1);
            split2(p2, h2, lo2); split2(p3, h3, lo3);
            int ks = ni >> 1;
            if ((ni & 1) == 0) {
                pf_h[ks][0] = pack2h(h0, h1);  pf_h[ks][1] = pack2h(h2, h3);
                pf_l[ks][0] = pack2h(lo0, lo1); pf_l[ks][1] = pack2h(lo2, lo3);
            } else {
                pf_h[ks][2] = pack2h(h0, h1);  pf_h[ks][3] = pack2h(h2, h3);
                pf_l[ks][2] = pack2h(lo0, lo1); pf_l[ks][3] = pack2h(lo2, lo3);
            }
        }
        s0 += __shfl_xor_sync(0xffffffffu, s0, 1);
        s0 += __shfl_xor_sync(0xffffffffu, s0, 2);
        s1 += __shfl_xor_sync(0xffffffffu, s1, 1);
        s1 += __shfl_xor_sync(0xffffffffu, s1, 2);
        l0 += s0; l1 += s1;
        m0 = mn0; m1 = mn1;

        const uint32_t vb_h = stg + 2u * AT_TILE;
        const uint32_t vb_l = stg + 3u * AT_TILE;
        #pragma unroll
        for (int ks = 0; ks < 4; ks++) {
            #pragma unroll
            for (int dbp = 0; dbp < 4; dbp++) {
                uint32_t raddr = (uint32_t)(ks * 16 + (lane & 15)) * AT_PITCH
                               + (uint32_t)dbp * 32 + ((lane >> 4) << 4);
                uint32_t vh[4], vl[4];
                ldsm4t(vh[0], vh[1], vh[2], vh[3], vb_h + raddr);
                mma16816(yacc[2*dbp],   pf_h[ks], vh + 0);
                mma16816(yacc[2*dbp+1], pf_h[ks], vh + 2);
                mma16816(yacc[2*dbp],   pf_l[ks], vh + 0);
                mma16816(yacc[2*dbp+1], pf_l[ks], vh + 2);
                ldsm4t(vl[0], vl[1], vl[2], vl[3], vb_l + raddr);
                mma16816(yacc[2*dbp],   pf_h[ks], vl + 0);
                mma16816(yacc[2*dbp+1], pf_h[ks], vl + 2);
            }
        }

        if (st + 2 <= qt) {
            __syncthreads();
            load_kv(st & 1, st + 2);
        }
    }

    float inv0 = 1.f / l0, inv1 = 1.f / l1;
    int r0g = qrow + wid * 16 + (lane >> 2);
    size_t base0 = (size_t)r0g * DD + h * 64;
    size_t base1 = base0 + (size_t)8 * DD;
    #pragma unroll
    for (int db = 0; db < 8; db++) {
        int cc = db * 8 + 2 * (lane & 3);
        __half h0, lo0, h1, lo1;
        split2(yacc[db][0] * inv0, h0, lo0);
        split2(yacc[db][1] * inv0, h1, lo1);
        *(__half2*)&Yh[base0 + cc] = __halves2half2(h0, h1);
        *(__half2*)&Yl[base0 + cc] = __halves2half2(lo0, lo1);
        split2(yacc[db][2] * inv1, h0, lo0);
        split2(yacc[db][3] * inv1, h1, lo1);
        *(__half2*)&Yh[base1 + cc] = __halves2half2(h0, h1);
        *(__half2*)&Yl[base1 + cc] = __halves2half2(lo0, lo1);
    }
}

// ---------------------------------------------------------------------------
// Fused embedding + positional encoding + LayerNorm(ln1, layer 0).
// ---------------------------------------------------------------------------
__global__ __launch_bounds__(256) void embed_ln_kernel(const int* __restrict__ tokens,
                                                       const float* __restrict__ emb,
                                                       const float* __restrict__ w,
                                                       const float* __restrict__ b,
                                                       float* __restrict__ x,
                                                       __half* __restrict__ yh,
                                                       __half* __restrict__ yl)
{
    __shared__ float red[8];
    int row = blockIdx.x;
    int tid = threadIdx.x;
    int bb  = row >> 11;
    int t   = row & (TT - 1);
    int tok = (t == 0) ? 0 : tokens[bb * TT + t - 1];

    int c = tid * 4;
    float v[4];
    #pragma unroll
    for (int j = 0; j < 4; j++) {
        int d = c + j;
        int k = d & 1;
        double e = (double)(d - k) / (double)DD;
        float freq = (float)exp(-e * 11.512925464970229);
        float arg = (float)t * freq + 1.5707963267948966f * (float)k;
        v[j] = emb[(size_t)tok * DD + d] + sinf(arg);
    }
    *(float4*)&x[(size_t)row * DD + c] = make_float4(v[0], v[1], v[2], v[3]);

    float s = v[0] + v[1] + v[2] + v[3];
    #pragma unroll
    for (int o = 16; o > 0; o >>= 1) s += __shfl_xor_sync(0xffffffffu, s, o);
    if ((tid & 31) == 0) red[tid >> 5] = s;
    __syncthreads();
    float tot = 0.f;
    #pragma unroll
    for (int i = 0; i < 8; i++) tot += red[i];
    float mean = tot * (1.0f / DD);
    __syncthreads();

    float dx0 = v[0]-mean, dx1 = v[1]-mean, dx2 = v[2]-mean, dx3 = v[3]-mean;
    float s2 = dx0*dx0 + dx1*dx1 + dx2*dx2 + dx3*dx3;
    #pragma unroll
    for (int o = 16; o > 0; o >>= 1) s2 += __shfl_xor_sync(0xffffffffu, s2, o);
    if ((tid & 31) == 0) red[tid >> 5] = s2;
    __syncthreads();
    float tot2 = 0.f;
    #pragma unroll
    for (int i = 0; i < 8; i++) tot2 += red[i];
    float inv = rsqrtf(tot2 * (1.0f / DD) + 1e-5f);

    float4 wv = *(const float4*)&w[c];
    float4 bv = *(const float4*)&b[c];
    float o0 = dx0 * inv * wv.x + bv.x;
    float o1 = dx1 * inv * wv.y + bv.y;
    float o2 = dx2 * inv * wv.z + bv.z;
    float o3 = dx3 * inv * wv.w + bv.w;
    __half h0, l0, h1, l1, h2, l2, h3, l3;
    split2(o0, h0, l0); split2(o1, h1, l1); split2(o2, h2, l2); split2(o3, h3, l3);
    size_t off = (size_t)row * DD + c;
    *(__half2*)&yh[off]     = __halves2half2(h0, h1);
    *(__half2*)&yh[off + 2] = __halves2half2(h2, h3);
    *(__half2*)&yl[off]     = __halves2half2(l0, l1);
    *(__half2*)&yl[off + 2] = __halves2half2(l2, l3);
}

// ---------------------------------------------------------------------------
// LayerNorm -> split fp16 hi/lo output
// ---------------------------------------------------------------------------
__global__ __launch_bounds__(256) void ln_split_kernel(const float* __restrict__ x,
                                                       __half* __restrict__ yh,
                                                       __half* __restrict__ yl,
                                                       const float* __restrict__ w,
                                                       const float* __restrict__ b)
{
    __shared__ float red[8];
    int row = blockIdx.x;
    int tid = threadIdx.x;
    const float* xr = x + (size_t)row * DD;
    float4 xv = *(const float4*)&xr[tid * 4];

    float s = xv.x + xv.y + xv.z + xv.w;
    #pragma unroll
    for (int o = 16; o > 0; o >>= 1) s += __shfl_xor_sync(0xffffffffu, s, o);
    if ((tid & 31) == 0) red[tid >> 5] = s;
    __syncthreads();
    float tot = 0.f;
    #pragma unroll
    for (int i = 0; i < 8; i++) tot += red[i];
    float mean = tot * (1.0f / DD);
    __syncthreads();

    float dx0 = xv.x - mean, dx1 = xv.y - mean, dx2 = xv.z - mean, dx3 = xv.w - mean;
    float s2 = dx0*dx0 + dx1*dx1 + dx2*dx2 + dx3*dx3;
    #pragma unroll
    for (int o = 16; o > 0; o >>= 1) s2 += __shfl_xor_sync(0xffffffffu, s2, o);
    if ((tid & 31) == 0) red[tid >> 5] = s2;
    __syncthreads();
    float tot2 = 0.f;
    #pragma unroll
    for (int i = 0; i < 8; i++) tot2 += red[i];
    float inv = rsqrtf(tot2 * (1.0f / DD) + 1e-5f);

    int c = tid * 4;
    float4 wv = *(const float4*)&w[c];
    float4 bv = *(const float4*)&b[c];
    float o0 = dx0 * inv * wv.x + bv.x;
    float o1 = dx1 * inv * wv.y + bv.y;
    float o2 = dx2 * inv * wv.z + bv.z;
    float o3 = dx3 * inv * wv.w + bv.w;
    __half h0, l0, h1, l1, h2, l2, h3, l3;
    split2(o0, h0, l0); split2(o1, h1, l1); split2(o2, h2, l2); split2(o3, h3, l3);
    size_t off = (size_t)row * DD + c;
    *(__half2*)&yh[off]     = __halves2half2(h0, h1);
    *(__half2*)&yh[off + 2] = __halves2half2(h2, h3);
    *(__half2*)&yl[off]     = __halves2half2(l0, l1);
    *(__half2*)&yl[off + 2] = __halves2half2(l2, l3);
}

// ---------------------------------------------------------------------------
// Weight conversion kernels (single fp16, vectorized x4)
// ---------------------------------------------------------------------------
__global__ void conv_kernel(const float* __restrict__ s,
                            __half* __restrict__ h, int n4)
{
    int i = blockIdx.x * blockDim.x + threadIdx.x;
    if (i >= n4) return;
    float4 v = *(const float4*)&s[i * 4];
    *(__half2*)&h[i*4]   = __halves2half2(__float2half(v.x), __float2half(v.y));
    *(__half2*)&h[i*4+2] = __halves2half2(__float2half(v.z), __float2half(v.w));
}

__global__ void pack_qkv_kernel(const float* __restrict__ wq,
                                const float* __restrict__ wk,
                                const float* __restrict__ wv,
                                __half* __restrict__ h)
{
    int i = blockIdx.x * blockDim.x + threadIdx.x;
    const int per_layer4 = QKVD * DD / 4;
    if (i >= LL * per_layer4) return;
    int lyr = i / per_layer4;
    int rem = i - lyr * per_layer4;
    int row = rem >> 8;
    int c4  = rem & 255;
    int which = row >> 10;
    int srow  = row & 1023;
    const float* src = (which == 0) ? wq : ((which == 1) ? wk : wv);
    float4 v = *(const float4*)&src[(size_t)lyr * (DD*DD) + (size_t)srow * DD + c4 * 4];
    size_t o = (size_t)i * 4;
    *(__half2*)&h[o]   = __halves2half2(__float2half(v.x), __float2half(v.y));
    *(__half2*)&h[o+2] = __halves2half2(__float2half(v.z), __float2half(v.w));
}

__global__ void transpose_wo_kernel(const float* __restrict__ wo,
                                    __half* __restrict__ h)
{
    int i = blockIdx.x * blockDim.x + threadIdx.x;
    if (i >= LL * DD * DD) return;
    int lyr = i >> 20;
    int rem = i & ((1 << 20) - 1);
    int nrow = rem >> 10;
    int kcol = rem & 1023;
    h[i] = __float2half(wo[((size_t)lyr << 20) + ((size_t)kcol << 10) + nrow]);
}

// ---------------------------------------------------------------------------
// Launch
// ---------------------------------------------------------------------------
extern "C" void kernel_launch(void* const* d_in, const int* in_sizes, int n_in,
                              void* d_out, int out_size)
{
    const int*   tokens = (const int*)  d_in[0];
    const float* emb    = (const float*)d_in[1];
    const float* ln1_w  = (const float*)d_in[2];
    const float* ln1_b  = (const float*)d_in[3];
    const float* w_q    = (const float*)d_in[4];
    const float* w_k    = (const float*)d_in[5];
    const float* w_v    = (const float*)d_in[6];
    const float* w_o    = (const float*)d_in[7];
    const float* ln2_w  = (const float*)d_in[8];
    const float* ln2_b  = (const float*)d_in[9];
    const float* w1     = (const float*)d_in[10];
    const float* b1     = (const float*)d_in[11];
    const float* w2     = (const float*)d_in[12];
    const float* b2     = (const float*)d_in[13];
    const float* ro_w   = (const float*)d_in[14];
    const float* ro_b   = (const float*)d_in[15];
    float* out = (float*)d_out;

    float *x;
    __half *qkvh, *qkvl, *xnh, *xnl, *yh, *yl, *hh, *hl, *xh, *xl;
    __half *wqkv, *wo, *w1w, *w2w, *ro;
    cudaGetSymbolAddress((void**)&x,    g_x);
    cudaGetSymbolAddress((void**)&qkvh, g_qkvh); cudaGetSymbolAddress((void**)&qkvl, g_qkvl);
    cudaGetSymbolAddress((void**)&xnh,  g_xnh);  cudaGetSymbolAddress((void**)&xnl, g_xnl);
    cudaGetSymbolAddress((void**)&yh,   g_yh);   cudaGetSymbolAddress((void**)&yl,  g_yl);
    cudaGetSymbolAddress((void**)&hh,   g_hh);   cudaGetSymbolAddress((void**)&hl,  g_hl);
    cudaGetSymbolAddress((void**)&xh,   g_xh);   cudaGetSymbolAddress((void**)&xl,  g_xl);
    cudaGetSymbolAddress((void**)&wqkv, g_wqkv);
    cudaGetSymbolAddress((void**)&wo,   g_wo);
    cudaGetSymbolAddress((void**)&w1w,  g_w1);
    cudaGetSymbolAddress((void**)&w2w,  g_w2);
    cudaGetSymbolAddress((void**)&ro,   g_ro);

    cudaFuncSetAttribute((const void*)gemm_mma<false,false,false,true,true>,
                         cudaFuncAttributeMaxDynamicSharedMemorySize, SMEM_B);
    cudaFuncSetAttribute((const void*)gemm_mma<false,false,true,false,true>,
                         cudaFuncAttributeMaxDynamicSharedMemorySize, SMEM_B);
    cudaFuncSetAttribute((const void*)gemm_mma<true,true,false,true,true>,
                         cudaFuncAttributeMaxDynamicSharedMemorySize, SMEM_B);
    cudaFuncSetAttribute((const void*)gemm_mma<true,false,true,false,true>,
                         cudaFuncAttributeMaxDynamicSharedMemorySize, SMEM_B);
    cudaFuncSetAttribute((const void*)gemm_mma<true,false,true,true,true>,
                         cudaFuncAttributeMaxDynamicSharedMemorySize, SMEM_B);
    cudaFuncSetAttribute((const void*)gemm_mma<true,false,false,false,false>,
                         cudaFuncAttributeMaxDynamicSharedMemorySize, SMEM_B);
    cudaFuncSetAttribute((const void*)attn_mma,
                         cudaFuncAttributeMaxDynamicSharedMemorySize, AT_SMEM);

    // grid: x = M-block (fast), y = N-block (slow)
    const dim3 gQKV(MM/128, QKVD/128);    // 32 x 24
    const dim3 gD  (MM/128, DD/128);      // 32 x 8
    const dim3 gH  (MM/128, HDIM/128);    // 32 x 32
    const dim3 gV  (MM/128, VV/128);      // 32 x 250
    const dim3 gA  (TT/64, BB*HH);        // 32 x 32

    pack_qkv_kernel<<<(LL*QKVD*DD/4 + 255)/256, 256>>>(w_q, w_k, w_v, wqkv);
    embed_ln_kernel<<<MM, 256>>>(tokens, emb, ln1_w, ln1_b, x, xnh, xnl);
    transpose_wo_kernel<<<(LL*DD*DD + 255)/256, 256>>>(w_o, wo);
    gemm_mma<false,false,false,true,true><<<gQKV, 128, SMEM_B>>>(
        xnh, xnl, wqkv, nullptr, nullptr, qkvh, qkvl, MM, QKVD, DD);
    conv_kernel<<<(LL*HDIM*DD/4 + 255)/256, 256>>>(w1, w1w, LL*HDIM*DD/4);
    conv_kernel<<<(LL*DD*HDIM/4 + 255)/256, 256>>>(w2, w2w, LL*DD*HDIM/4);
    conv_kernel<<<(VV*DD/4 + 255)/256, 256>>>(ro_w, ro, VV*DD/4);

    for (int l = 0; l < LL; l++) {
        const __half* wqkv_l = wqkv + (size_t)l * QKVD * DD;
        const __half* wo_l   = wo   + (size_t)l * DD * DD;
        const __half* w1_l   = w1w  + (size_t)l * HDIM * DD;
        const __half* w2_l   = w2w  + (size_t)l * DD * HDIM;

        if (l > 0) {
            ln_split_kernel<<<MM, 256>>>(x, xnh, xnl, ln1_w + (size_t)l*DD, ln1_b + (size_t)l*DD);
            gemm_mma<false,false,false,true,true><<<gQKV, 128, SMEM_B>>>(
                xnh, xnl, wqkv_l, nullptr, nullptr, qkvh, qkvl, MM, QKVD, DD);
        }

        attn_mma<<<gA, 128, AT_SMEM>>>(qkvh, qkvl, yh, yl);

        gemm_mma<false,false,true,false,true><<<gD, 128, SMEM_B>>>(
            yh, yl, wo_l, nullptr, x, nullptr, nullptr, MM, DD, DD);

        ln_split_kernel<<<MM, 256>>>(x, xnh, xnl, ln2_w + (size_t)l*DD, ln2_b + (size_t)l*DD);

        gemm_mma<true,true,false,true,true><<<gH, 128, SMEM_B>>>(
            xnh, xnl, w1_l, b1 + (size_t)l*HDIM, nullptr, hh, hl, MM, HDIM, DD);

        if (l < LL - 1) {
            gemm_mma<true,false,true,false,true><<<gD, 128, SMEM_B>>>(
                hh, hl, w2_l, b2 + (size_t)l*DD, x, nullptr, nullptr, MM, DD, HDIM);
        } else {
            gemm_mma<true,false,true,true,true><<<gD, 128, SMEM_B>>>(
                hh, hl, w2_l, b2 + (size_t)l*DD, x, xh, xl, MM, DD, HDIM);
        }
    }

    // readout: out = x @ ro_w^T + ro_b — single-term A (error not amplified)
    gemm_mma<true,false,false,false,false><<<gV, 128, SMEM_B>>>(
        xh, xl, ro, ro_b, out, nullptr, nullptr, MM, VV, DD);
}